// round 7
// baseline (speedup 1.0000x reference)
#include <cuda_runtime.h>
#include <cstdint>

#define BB 32
#define NN 512
#define FF 64
#define HH 8
#define ROWS (BB*NN)   // 16384

typedef unsigned long long ull;

// ---------------- scratch (static device globals; no allocation) ----------------
__device__ __align__(16) int16_t g_nbr[ROWS * NN];      // 16 MB neighbor lists
__device__              int      g_cnt[ROWS];
__device__ __align__(16) float   g_hp0[ROWS * FF];      // 4 MB
__device__ __align__(16) float   g_s0t[ROWS * HH];      // node-major [row][h]
__device__ __align__(16) float   g_d0t[ROWS * HH];
__device__ __align__(16) float   g_x1[ROWS * (HH*FF)];  // 32 MB (elu'd concat)
__device__ __align__(16) float   g_hp1[ROWS * FF];
__device__ __align__(16) float   g_s1t[ROWS * HH];
__device__ __align__(16) float   g_d1t[ROWS * HH];

// ---------------- packed f32x2 helpers ------------------------------------------
static __device__ __forceinline__ ull fma2(ull a, ull b, ull c) {
    ull r;
    asm("fma.rn.f32x2 %0, %1, %2, %3;" : "=l"(r) : "l"(a), "l"(b), "l"(c));
    return r;
}
static __device__ __forceinline__ ull mul2(ull a, ull b) {
    ull r;
    asm("mul.rn.f32x2 %0, %1, %2;" : "=l"(r) : "l"(a), "l"(b));
    return r;
}
static __device__ __forceinline__ ull pk2(float x, float y) {
    ull r;
    asm("mov.b64 %0, {%1, %2};" : "=l"(r) : "f"(x), "f"(y));
    return r;
}
static __device__ __forceinline__ void upk2(ull v, float& x, float& y) {
    asm("mov.b64 {%0, %1}, %2;" : "=f"(x), "=f"(y) : "l"(v));
}

// ---------------- kernel 1: compact adjacency rows into neighbor lists ----------
__global__ void __launch_bounds__(256) k_build_nbr(const float* __restrict__ adj) {
    const int row  = (blockIdx.x << 3) + (threadIdx.x >> 5);
    const int lane = threadIdx.x & 31;
    const int i    = row & (NN - 1);
    const float* arow = adj + ((size_t)row << 9);
    int16_t* outp = g_nbr + ((size_t)row << 9);
    int off = 0;
    #pragma unroll
    for (int base = 0; base < NN; base += 32) {
        const int j = base + lane;
        const bool p = (arow[j] != 0.f) || (j == i);   // diag forced to 1
        const unsigned msk = __ballot_sync(0xffffffffu, p);
        if (p) outp[off + __popc(msk & ((1u << lane) - 1u))] = (int16_t)j;
        off += __popc(msk);
    }
    if (lane == 0) g_cnt[row] = off;
}

// ---------------- kernel 2: GEMM  C[M,64] = A[M,K] @ B[K,64]  -------------------
template<int K, int LAYER>
__global__ void __launch_bounds__(256) k_gemm(const float* __restrict__ Aext,
                                              const float* __restrict__ Bw) {
    const float* __restrict__ A = (LAYER == 0) ? Aext : g_x1;
    float* __restrict__ C = (LAYER == 0) ? g_hp0 : g_hp1;
    __shared__ float As[32][72];   // As[kk][m] (transposed)
    __shared__ float Bs[32][72];   // Bs[kk][n]
    const int bm = blockIdx.x << 6;
    const int t  = threadIdx.x;
    const int ty = t >> 4, tx = t & 15;
    ull acc[4][2];
    #pragma unroll
    for (int r = 0; r < 4; r++) { acc[r][0] = 0ull; acc[r][1] = 0ull; }

    for (int k0 = 0; k0 < K; k0 += 32) {
        #pragma unroll
        for (int l = 0; l < 2; l++) {
            const int idx = t + (l << 8);          // 0..511
            const int m  = idx >> 3;
            const int kq = (idx & 7) << 2;
            float4 av = *(const float4*)(A + (size_t)(bm + m) * K + k0 + kq);
            As[kq + 0][m] = av.x; As[kq + 1][m] = av.y;
            As[kq + 2][m] = av.z; As[kq + 3][m] = av.w;
            const int kk = idx >> 4;
            const int nq = (idx & 15) << 2;
            *(float4*)&Bs[kk][nq] = *(const float4*)(Bw + (size_t)(k0 + kk) * 64 + nq);
        }
        __syncthreads();
        #pragma unroll
        for (int kk = 0; kk < 32; kk++) {
            const float4 a = *(const float4*)&As[kk][ty << 2];
            const longlong2 bv = *(const longlong2*)&Bs[kk][tx << 2];
            const ull b0 = (ull)bv.x;
            const ull b1 = (ull)bv.y;
            const ull a0 = pk2(a.x, a.x), a1 = pk2(a.y, a.y);
            const ull a2 = pk2(a.z, a.z), a3 = pk2(a.w, a.w);
            acc[0][0] = fma2(a0, b0, acc[0][0]); acc[0][1] = fma2(a0, b1, acc[0][1]);
            acc[1][0] = fma2(a1, b0, acc[1][0]); acc[1][1] = fma2(a1, b1, acc[1][1]);
            acc[2][0] = fma2(a2, b0, acc[2][0]); acc[2][1] = fma2(a2, b1, acc[2][1]);
            acc[3][0] = fma2(a3, b0, acc[3][0]); acc[3][1] = fma2(a3, b1, acc[3][1]);
        }
        __syncthreads();
    }
    #pragma unroll
    for (int r = 0; r < 4; r++) {
        float o0, o1, o2, o3;
        upk2(acc[r][0], o0, o1); upk2(acc[r][1], o2, o3);
        *(float4*)(C + (size_t)(bm + (ty << 2) + r) * 64 + (tx << 2)) =
            make_float4(o0, o1, o2, o3);
    }
}

// ---------------- kernel 3: s/d projections, stored NODE-MAJOR [row][h] ---------
template<int LAYER>
__global__ void __launch_bounds__(256) k_sd(const float* __restrict__ asrc,
                                            const float* __restrict__ adst) {
    const float* __restrict__ hp = (LAYER == 0) ? g_hp0 : g_hp1;
    float* __restrict__ s = (LAYER == 0) ? g_s0t : g_s1t;
    float* __restrict__ d = (LAYER == 0) ? g_d0t : g_d1t;
    const int row  = (blockIdx.x << 3) + (threadIdx.x >> 5);
    const int lane = threadIdx.x & 31;
    const float h0 = hp[(size_t)row * 64 + lane];
    const float h1 = hp[(size_t)row * 64 + 32 + lane];
    float ps[8], pd[8];
    #pragma unroll
    for (int h = 0; h < 8; h++) {
        ps[h] = h0 * asrc[(lane << 3) + h] + h1 * asrc[((lane + 32) << 3) + h];
        pd[h] = h0 * adst[(lane << 3) + h] + h1 * adst[((lane + 32) << 3) + h];
    }
    #pragma unroll
    for (int h = 0; h < 8; h++) {
        #pragma unroll
        for (int o = 16; o; o >>= 1) {
            ps[h] += __shfl_xor_sync(0xffffffffu, ps[h], o);
            pd[h] += __shfl_xor_sync(0xffffffffu, pd[h], o);
        }
    }
    if (lane == 0) {
        *(float4*)(s + (row << 3))     = make_float4(ps[0], ps[1], ps[2], ps[3]);
        *(float4*)(s + (row << 3) + 4) = make_float4(ps[4], ps[5], ps[6], ps[7]);
        *(float4*)(d + (row << 3))     = make_float4(pd[0], pd[1], pd[2], pd[3]);
        *(float4*)(d + (row << 3) + 4) = make_float4(pd[4], pd[5], pd[6], pd[7]);
    }
}

// ---------------- unified one-pass aggregation, BATCH-LOCAL CTAs ----------------
// grid = 128 CTAs x 512 thr (16 warps). CTA c: batch b = c>>2, quarter q = c&3.
// Each warp processes 8 consecutive rows of that batch; all gathers (hp[b] 128KB,
// d[b] 16KB) stay inside one SM's L1 for the whole CTA lifetime.
// LAYER 0: out = elu(concat_h softmax_h @ hp)  -> g_x1
// LAYER 1: out = mean_h softmax_h @ hp         -> final output
template<int LAYER>
__global__ void __launch_bounds__(512) k_agg(float* __restrict__ outp) {
    __shared__ __align__(16) float2 s_w[16][32][8];  // per-warp chunk weights {w,w}
    __shared__ int s_off[16][32];                    // per-warp hp byte offsets
    const int wi = threadIdx.x >> 5, lane = threadIdx.x & 31;
    const int b = blockIdx.x >> 2, q = blockIdx.x & 3;
    const float* __restrict__ dtb =
        ((LAYER == 0) ? g_d0t : g_d1t) + ((size_t)b << 12);      // [i][h]
    const char*  __restrict__ hpl =
        (const char*)(((LAYER == 0) ? g_hp0 : g_hp1) + ((size_t)b << 15))
        + (lane << 3);                                           // lane's 8B in row
    const float* __restrict__ st = (LAYER == 0) ? g_s0t : g_s1t;

    for (int r = 0; r < 8; r++) {
        const int i   = (q << 7) + (wi << 3) + r;    // node index within batch
        const int row = (b << 9) + i;
        const int cnt = g_cnt[row];
        const int16_t* __restrict__ nbrrow = g_nbr + ((size_t)row << 9);

        float sh[8], Zl[8];
        {
            const float4 s0 = *(const float4*)(st + (row << 3));
            const float4 s1 = *(const float4*)(st + (row << 3) + 4);
            sh[0] = s0.x; sh[1] = s0.y; sh[2] = s0.z; sh[3] = s0.w;
            sh[4] = s1.x; sh[5] = s1.y; sh[6] = s1.z; sh[7] = s1.w;
        }
        ull acc[8];
        #pragma unroll
        for (int h = 0; h < 8; h++) { Zl[h] = 0.f; acc[h] = 0ull; }

        for (int base = 0; base < cnt; base += 32) {
            const int nc = min(32, cnt - base);
            // weight phase: lane <-> neighbor
            float wt[8];
            #pragma unroll
            for (int h = 0; h < 8; h++) wt[h] = 0.f;
            int off = i << 8;                          // valid pad address
            if (lane < nc) {
                const int j = (int)nbrrow[base + lane];
                off = j << 8;
                const float4 da = *(const float4*)(dtb + (j << 3));
                const float4 db = *(const float4*)(dtb + (j << 3) + 4);
                float dv[8] = {da.x, da.y, da.z, da.w, db.x, db.y, db.z, db.w};
                #pragma unroll
                for (int h = 0; h < 8; h++) {
                    const float ev = sh[h] + dv[h];
                    const float lv = fmaxf(ev, 0.2f * ev);
                    const float e  = (lv != 0.f) ? __expf(lv) : 0.f;
                    wt[h] = e;
                    Zl[h] += e;
                }
            }
            s_off[wi][lane] = off;
            {
                float4* wp = (float4*)&s_w[wi][lane][0];
                wp[0] = make_float4(wt[0], wt[0], wt[1], wt[1]);
                wp[1] = make_float4(wt[2], wt[2], wt[3], wt[3]);
                wp[2] = make_float4(wt[4], wt[4], wt[5], wt[5]);
                wp[3] = make_float4(wt[6], wt[6], wt[7], wt[7]);
            }
            __syncwarp();
            // FMA phase: groups of 8 with batched loads (MLP=8, L1-resident)
            for (int g = 0; g < nc; g += 8) {
                ull hpv[8];
                #pragma unroll
                for (int qq = 0; qq < 8; qq++)
                    hpv[qq] = *(const ull*)(hpl + s_off[wi][g + qq]);
                #pragma unroll
                for (int qq = 0; qq < 8; qq++) {
                    const longlong2* wp2 = (const longlong2*)&s_w[wi][g + qq][0];
                    const longlong2 w01 = wp2[0], w23 = wp2[1];
                    const longlong2 w45 = wp2[2], w67 = wp2[3];
                    acc[0] = fma2((ull)w01.x, hpv[qq], acc[0]);
                    acc[1] = fma2((ull)w01.y, hpv[qq], acc[1]);
                    acc[2] = fma2((ull)w23.x, hpv[qq], acc[2]);
                    acc[3] = fma2((ull)w23.y, hpv[qq], acc[3]);
                    acc[4] = fma2((ull)w45.x, hpv[qq], acc[4]);
                    acc[5] = fma2((ull)w45.y, hpv[qq], acc[5]);
                    acc[6] = fma2((ull)w67.x, hpv[qq], acc[6]);
                    acc[7] = fma2((ull)w67.y, hpv[qq], acc[7]);
                }
            }
            __syncwarp();
        }
        // combine per-lane Z
        #pragma unroll
        for (int h = 0; h < 8; h++)
            #pragma unroll
            for (int o = 16; o; o >>= 1)
                Zl[h] += __shfl_xor_sync(0xffffffffu, Zl[h], o);

        if (LAYER == 0) {
            float* xout = outp + ((size_t)row << 9);
            #pragma unroll
            for (int h = 0; h < 8; h++) {
                const float rz = __fdividef(1.f, Zl[h]);
                float xf, yf; upk2(mul2(acc[h], pk2(rz, rz)), xf, yf);
                xf = xf > 0.f ? xf : (__expf(xf) - 1.f);
                yf = yf > 0.f ? yf : (__expf(yf) - 1.f);
                ((float2*)(xout + (h << 6)))[lane] = make_float2(xf, yf);
            }
        } else {
            ull ov = 0ull;
            #pragma unroll
            for (int h = 0; h < 8; h++) {
                const float rz = __fdividef(0.125f, Zl[h]);
                ov = fma2(acc[h], pk2(rz, rz), ov);
            }
            float xf, yf; upk2(ov, xf, yf);
            ((float2*)(outp + ((size_t)row << 6)))[lane] = make_float2(xf, yf);
        }
    }
}

// ---------------- launch --------------------------------------------------------
extern "C" void kernel_launch(void* const* d_in, const int* in_sizes, int n_in,
                              void* d_out, int out_size) {
    const float* x     = (const float*)d_in[0];
    const float* adj   = (const float*)d_in[1];
    const float* W0    = (const float*)d_in[4];
    const float* asrc0 = (const float*)d_in[5];
    const float* adst0 = (const float*)d_in[6];
    const float* W1    = (const float*)d_in[7];
    const float* asrc1 = (const float*)d_in[8];
    const float* adst1 = (const float*)d_in[9];
    float* out = (float*)d_out;

    k_build_nbr<<<ROWS / 8, 256>>>(adj);
    k_gemm<64, 0><<<ROWS / 64, 256>>>(x, W0);
    k_sd<0><<<ROWS / 8, 256>>>(asrc0, adst0);
    float* x1p;  cudaGetSymbolAddress((void**)&x1p, g_x1);
    k_agg<0><<<BB * 4, 512>>>(x1p);
    k_gemm<512, 1><<<ROWS / 64, 256>>>(nullptr, W1);
    k_sd<1><<<ROWS / 8, 256>>>(asrc1, adst1);
    k_agg<1><<<BB * 4, 512>>>(out);
}

// round 8
// speedup vs baseline: 1.1862x; 1.1862x over previous
#include <cuda_runtime.h>
#include <cstdint>

#define BB 32
#define NN 512
#define FF 64
#define HH 8
#define ROWS (BB*NN)   // 16384

typedef unsigned long long ull;

// ---------------- scratch (static device globals; no allocation) ----------------
__device__ __align__(16) int16_t g_nbr[ROWS * NN];      // 16 MB neighbor lists
__device__              int      g_cnt[ROWS];
__device__ __align__(16) float   g_hp0[ROWS * FF];      // 4 MB
__device__ __align__(16) float   g_s0t[ROWS * HH];      // node-major [row][h]
__device__ __align__(16) float   g_d0t[ROWS * HH];
__device__ __align__(16) float   g_x1[ROWS * (HH*FF)];  // 32 MB (elu'd concat)
__device__ __align__(16) float   g_hp1[ROWS * FF];
__device__ __align__(16) float   g_s1t[ROWS * HH];
__device__ __align__(16) float   g_d1t[ROWS * HH];

// ---------------- packed f32x2 helpers ------------------------------------------
static __device__ __forceinline__ ull fma2(ull a, ull b, ull c) {
    ull r;
    asm("fma.rn.f32x2 %0, %1, %2, %3;" : "=l"(r) : "l"(a), "l"(b), "l"(c));
    return r;
}
static __device__ __forceinline__ ull mul2(ull a, ull b) {
    ull r;
    asm("mul.rn.f32x2 %0, %1, %2;" : "=l"(r) : "l"(a), "l"(b));
    return r;
}
static __device__ __forceinline__ ull pk2(float x, float y) {
    ull r;
    asm("mov.b64 %0, {%1, %2};" : "=l"(r) : "f"(x), "f"(y));
    return r;
}
static __device__ __forceinline__ void upk2(ull v, float& x, float& y) {
    asm("mov.b64 {%0, %1}, %2;" : "=f"(x), "=f"(y) : "l"(v));
}

// ---------------- kernel 1: compact adjacency rows into neighbor lists ----------
__global__ void __launch_bounds__(256) k_build_nbr(const float* __restrict__ adj) {
    const int row  = (blockIdx.x << 3) + (threadIdx.x >> 5);
    const int lane = threadIdx.x & 31;
    const int i    = row & (NN - 1);
    const float* arow = adj + ((size_t)row << 9);
    int16_t* outp = g_nbr + ((size_t)row << 9);
    int off = 0;
    #pragma unroll
    for (int base = 0; base < NN; base += 32) {
        const int j = base + lane;
        const bool p = (arow[j] != 0.f) || (j == i);   // diag forced to 1
        const unsigned msk = __ballot_sync(0xffffffffu, p);
        if (p) outp[off + __popc(msk & ((1u << lane) - 1u))] = (int16_t)j;
        off += __popc(msk);
    }
    if (lane == 0) g_cnt[row] = off;
}

// ---------------- kernel 2a: layer-0 GEMM  C[M,64] = A[M,64] @ B[64,64] ---------
__global__ void __launch_bounds__(256) k_gemm0(const float* __restrict__ A,
                                               const float* __restrict__ Bw) {
    float* __restrict__ C = g_hp0;
    __shared__ float As[32][72];   // As[kk][m] (transposed)
    __shared__ float Bs[32][72];   // Bs[kk][n]
    const int bm = blockIdx.x << 6;
    const int t  = threadIdx.x;
    const int ty = t >> 4, tx = t & 15;
    ull acc[4][2];
    #pragma unroll
    for (int r = 0; r < 4; r++) { acc[r][0] = 0ull; acc[r][1] = 0ull; }

    for (int k0 = 0; k0 < 64; k0 += 32) {
        #pragma unroll
        for (int l = 0; l < 2; l++) {
            const int idx = t + (l << 8);          // 0..511
            const int m  = idx >> 3;
            const int kq = (idx & 7) << 2;
            float4 av = *(const float4*)(A + (size_t)(bm + m) * 64 + k0 + kq);
            As[kq + 0][m] = av.x; As[kq + 1][m] = av.y;
            As[kq + 2][m] = av.z; As[kq + 3][m] = av.w;
            const int kk = idx >> 4;
            const int nq = (idx & 15) << 2;
            *(float4*)&Bs[kk][nq] = *(const float4*)(Bw + (size_t)(k0 + kk) * 64 + nq);
        }
        __syncthreads();
        #pragma unroll
        for (int kk = 0; kk < 32; kk++) {
            const float4 a = *(const float4*)&As[kk][ty << 2];
            const longlong2 bv = *(const longlong2*)&Bs[kk][tx << 2];
            const ull b0 = (ull)bv.x;
            const ull b1 = (ull)bv.y;
            const ull a0 = pk2(a.x, a.x), a1 = pk2(a.y, a.y);
            const ull a2 = pk2(a.z, a.z), a3 = pk2(a.w, a.w);
            acc[0][0] = fma2(a0, b0, acc[0][0]); acc[0][1] = fma2(a0, b1, acc[0][1]);
            acc[1][0] = fma2(a1, b0, acc[1][0]); acc[1][1] = fma2(a1, b1, acc[1][1]);
            acc[2][0] = fma2(a2, b0, acc[2][0]); acc[2][1] = fma2(a2, b1, acc[2][1]);
            acc[3][0] = fma2(a3, b0, acc[3][0]); acc[3][1] = fma2(a3, b1, acc[3][1]);
        }
        __syncthreads();
    }
    #pragma unroll
    for (int r = 0; r < 4; r++) {
        float o0, o1, o2, o3;
        upk2(acc[r][0], o0, o1); upk2(acc[r][1], o2, o3);
        *(float4*)(C + (size_t)(bm + (ty << 2) + r) * 64 + (tx << 2)) =
            make_float4(o0, o1, o2, o3);
    }
}

// ---------------- kernel 2b: layer-1 GEMM  C[M,64] = x1[M,512] @ W1[512,64] -----
// BM=128, BN=64, BK=32, 256 thr, 8x4 micro-tile (16 FFMA2 per 3 LDS.128).
__global__ void __launch_bounds__(256) k_gemm1(const float* __restrict__ Bw) {
    const float* __restrict__ A = g_x1;
    float* __restrict__ C = g_hp1;
    __shared__ float As[32][136];  // As[kk][m] (transposed), +8 pad
    __shared__ float Bs[32][72];
    const int bm = blockIdx.x << 7;
    const int t  = threadIdx.x;
    const int ty = t >> 4, tx = t & 15;   // ty: 8-row group, tx: 4-col group
    ull acc[8][2];
    #pragma unroll
    for (int r = 0; r < 8; r++) { acc[r][0] = 0ull; acc[r][1] = 0ull; }

    for (int k0 = 0; k0 < 512; k0 += 32) {
        #pragma unroll
        for (int l = 0; l < 4; l++) {
            const int idx = t + (l << 8);          // 0..1023 (float4 units)
            const int m  = idx >> 3;               // 0..127
            const int kq = (idx & 7) << 2;
            float4 av = *(const float4*)(A + (size_t)(bm + m) * 512 + k0 + kq);
            As[kq + 0][m] = av.x; As[kq + 1][m] = av.y;
            As[kq + 2][m] = av.z; As[kq + 3][m] = av.w;
        }
        #pragma unroll
        for (int l = 0; l < 2; l++) {
            const int idx = t + (l << 8);          // 0..511
            const int kk = idx >> 4;
            const int nq = (idx & 15) << 2;
            *(float4*)&Bs[kk][nq] = *(const float4*)(Bw + (size_t)(k0 + kk) * 64 + nq);
        }
        __syncthreads();
        #pragma unroll
        for (int kk = 0; kk < 32; kk++) {
            const float4 a0v = *(const float4*)&As[kk][ty << 3];
            const float4 a1v = *(const float4*)&As[kk][(ty << 3) + 4];
            const longlong2 bv = *(const longlong2*)&Bs[kk][tx << 2];
            const ull b0 = (ull)bv.x, b1 = (ull)bv.y;
            const float ar[8] = {a0v.x, a0v.y, a0v.z, a0v.w,
                                 a1v.x, a1v.y, a1v.z, a1v.w};
            #pragma unroll
            for (int r = 0; r < 8; r++) {
                const ull av2 = pk2(ar[r], ar[r]);
                acc[r][0] = fma2(av2, b0, acc[r][0]);
                acc[r][1] = fma2(av2, b1, acc[r][1]);
            }
        }
        __syncthreads();
    }
    #pragma unroll
    for (int r = 0; r < 8; r++) {
        float o0, o1, o2, o3;
        upk2(acc[r][0], o0, o1); upk2(acc[r][1], o2, o3);
        *(float4*)(C + (size_t)(bm + (ty << 3) + r) * 64 + (tx << 2)) =
            make_float4(o0, o1, o2, o3);
    }
}

// ---------------- kernel 3: s/d projections, stored NODE-MAJOR [row][h] ---------
template<int LAYER>
__global__ void __launch_bounds__(256) k_sd(const float* __restrict__ asrc,
                                            const float* __restrict__ adst) {
    const float* __restrict__ hp = (LAYER == 0) ? g_hp0 : g_hp1;
    float* __restrict__ s = (LAYER == 0) ? g_s0t : g_s1t;
    float* __restrict__ d = (LAYER == 0) ? g_d0t : g_d1t;
    const int row  = (blockIdx.x << 3) + (threadIdx.x >> 5);
    const int lane = threadIdx.x & 31;
    const float h0 = hp[(size_t)row * 64 + lane];
    const float h1 = hp[(size_t)row * 64 + 32 + lane];
    float ps[8], pd[8];
    #pragma unroll
    for (int h = 0; h < 8; h++) {
        ps[h] = h0 * asrc[(lane << 3) + h] + h1 * asrc[((lane + 32) << 3) + h];
        pd[h] = h0 * adst[(lane << 3) + h] + h1 * adst[((lane + 32) << 3) + h];
    }
    #pragma unroll
    for (int h = 0; h < 8; h++) {
        #pragma unroll
        for (int o = 16; o; o >>= 1) {
            ps[h] += __shfl_xor_sync(0xffffffffu, ps[h], o);
            pd[h] += __shfl_xor_sync(0xffffffffu, pd[h], o);
        }
    }
    if (lane == 0) {
        *(float4*)(s + (row << 3))     = make_float4(ps[0], ps[1], ps[2], ps[3]);
        *(float4*)(s + (row << 3) + 4) = make_float4(ps[4], ps[5], ps[6], ps[7]);
        *(float4*)(d + (row << 3))     = make_float4(pd[0], pd[1], pd[2], pd[3]);
        *(float4*)(d + (row << 3) + 4) = make_float4(pd[4], pd[5], pd[6], pd[7]);
    }
}

// ---------------- kernel 4: layer-1 one-pass aggregate (R6 body, static trips) --
__global__ void __launch_bounds__(128) k_agg1() {
    __shared__ __align__(16) float2 s_w[4][32][8];   // chunk weights, pre-dup {w,w}
    __shared__ int s_off[4][32];                     // chunk hp byte offsets (j<<8)
    const int w = threadIdx.x >> 5, lane = threadIdx.x & 31;
    const int row = (blockIdx.x << 2) + w;
    const int b = row >> 9, i = row & (NN - 1);
    const int cnt = g_cnt[row];
    const int16_t* __restrict__ nbrrow = g_nbr + ((size_t)row << 9);
    const float* __restrict__ dtb = g_d0t + ((size_t)b << 12);   // [i][h]
    const char*  __restrict__ hpl =
        (const char*)(g_hp0 + ((size_t)b << 15)) + (lane << 3);  // lane's 8B in row

    float sh[8], Zl[8];
    {
        const float4 s0 = *(const float4*)(g_s0t + (row << 3));
        const float4 s1 = *(const float4*)(g_s0t + (row << 3) + 4);
        sh[0] = s0.x; sh[1] = s0.y; sh[2] = s0.z; sh[3] = s0.w;
        sh[4] = s1.x; sh[5] = s1.y; sh[6] = s1.z; sh[7] = s1.w;
    }
    ull acc[8];
    #pragma unroll
    for (int h = 0; h < 8; h++) { Zl[h] = 0.f; acc[h] = 0ull; }

    for (int base = 0; base < cnt; base += 32) {
        // weight phase: lane <-> neighbor (pad lanes: wt=0, valid self offset)
        float wt[8];
        #pragma unroll
        for (int h = 0; h < 8; h++) wt[h] = 0.f;
        int off = i << 8;
        if (base + lane < cnt) {
            const int j = (int)nbrrow[base + lane];
            off = j << 8;
            const float4 da = *(const float4*)(dtb + (j << 3));
            const float4 db = *(const float4*)(dtb + (j << 3) + 4);
            float dv[8] = {da.x, da.y, da.z, da.w, db.x, db.y, db.z, db.w};
            #pragma unroll
            for (int h = 0; h < 8; h++) {
                const float ev = sh[h] + dv[h];
                const float lv = fmaxf(ev, 0.2f * ev);
                const float e  = (lv != 0.f) ? __expf(lv) : 0.f;
                wt[h] = e;
                Zl[h] += e;
            }
        }
        s_off[w][lane] = off;
        {
            float4* wp = (float4*)&s_w[w][lane][0];
            wp[0] = make_float4(wt[0], wt[0], wt[1], wt[1]);
            wp[1] = make_float4(wt[2], wt[2], wt[3], wt[3]);
            wp[2] = make_float4(wt[4], wt[4], wt[5], wt[5]);
            wp[3] = make_float4(wt[6], wt[6], wt[7], wt[7]);
        }
        __syncwarp();
        // FMA phase: full 32, static trip count, groups of 8 (MLP=8)
        #pragma unroll
        for (int g = 0; g < 4; g++) {
            ull hpv[8];
            #pragma unroll
            for (int q = 0; q < 8; q++)
                hpv[q] = *(const ull*)(hpl + s_off[w][(g << 3) + q]);
            #pragma unroll
            for (int q = 0; q < 8; q++) {
                const longlong2* wp2 = (const longlong2*)&s_w[w][(g << 3) + q][0];
                const longlong2 w01 = wp2[0], w23 = wp2[1];
                const longlong2 w45 = wp2[2], w67 = wp2[3];
                acc[0] = fma2((ull)w01.x, hpv[q], acc[0]);
                acc[1] = fma2((ull)w01.y, hpv[q], acc[1]);
                acc[2] = fma2((ull)w23.x, hpv[q], acc[2]);
                acc[3] = fma2((ull)w23.y, hpv[q], acc[3]);
                acc[4] = fma2((ull)w45.x, hpv[q], acc[4]);
                acc[5] = fma2((ull)w45.y, hpv[q], acc[5]);
                acc[6] = fma2((ull)w67.x, hpv[q], acc[6]);
                acc[7] = fma2((ull)w67.y, hpv[q], acc[7]);
            }
        }
        __syncwarp();
    }
    #pragma unroll
    for (int h = 0; h < 8; h++)
        #pragma unroll
        for (int o = 16; o; o >>= 1)
            Zl[h] += __shfl_xor_sync(0xffffffffu, Zl[h], o);
    float* xout = g_x1 + ((size_t)row << 9);
    #pragma unroll
    for (int h = 0; h < 8; h++) {
        const float rz = __fdividef(1.f, Zl[h]);
        float xf, yf; upk2(mul2(acc[h], pk2(rz, rz)), xf, yf);
        xf = xf > 0.f ? xf : (__expf(xf) - 1.f);
        yf = yf > 0.f ? yf : (__expf(yf) - 1.f);
        ((float2*)(xout + (h << 6)))[lane] = make_float2(xf, yf);
    }
}

// ---------------- kernel 5: layer-2 two-pass (Z sweep, then scalar-weight FMA) --
__global__ void __launch_bounds__(128) k_agg2(float* __restrict__ out) {
    __shared__ __align__(16) float2 s_wb[4][32];
    __shared__ int s_off[4][32];
    const int w = threadIdx.x >> 5, lane = threadIdx.x & 31;
    const int row = (blockIdx.x << 2) + w;
    const int b = row >> 9, i = row & (NN - 1);
    const int cnt = g_cnt[row];
    const int16_t* __restrict__ nbrrow = g_nbr + ((size_t)row << 9);
    const float* __restrict__ dtb = g_d1t + ((size_t)b << 12);
    const char*  __restrict__ hpl =
        (const char*)(g_hp1 + ((size_t)b << 15)) + (lane << 3);

    float sh[8], Zl[8];
    {
        const float4 s0 = *(const float4*)(g_s1t + (row << 3));
        const float4 s1 = *(const float4*)(g_s1t + (row << 3) + 4);
        sh[0] = s0.x; sh[1] = s0.y; sh[2] = s0.z; sh[3] = s0.w;
        sh[4] = s1.x; sh[5] = s1.y; sh[6] = s1.z; sh[7] = s1.w;
    }
    #pragma unroll
    for (int h = 0; h < 8; h++) Zl[h] = 0.f;

    // pass 1: per-lane Z over strided neighbors
    #pragma unroll 2
    for (int p = lane; p < cnt; p += 32) {
        const int j = (int)nbrrow[p];
        const float4 da = *(const float4*)(dtb + (j << 3));
        const float4 db = *(const float4*)(dtb + (j << 3) + 4);
        float dv[8] = {da.x, da.y, da.z, da.w, db.x, db.y, db.z, db.w};
        #pragma unroll
        for (int h = 0; h < 8; h++) {
            const float ev = sh[h] + dv[h];
            const float lv = fmaxf(ev, 0.2f * ev);
            if (lv != 0.f) Zl[h] += __expf(lv);
        }
    }
    #pragma unroll
    for (int h = 0; h < 8; h++)
        #pragma unroll
        for (int o = 16; o; o >>= 1)
            Zl[h] += __shfl_xor_sync(0xffffffffu, Zl[h], o);
    float rz8[8];
    #pragma unroll
    for (int h = 0; h < 8; h++) rz8[h] = __fdividef(0.125f, Zl[h]);

    // pass 2: scalar weights (head-mean folded) + FMA, static trips
    ull acc = 0ull;
    for (int base = 0; base < cnt; base += 32) {
        float ws = 0.f;
        int off = i << 8;
        if (base + lane < cnt) {
            const int j = (int)nbrrow[base + lane];
            off = j << 8;
            const float4 da = *(const float4*)(dtb + (j << 3));
            const float4 db = *(const float4*)(dtb + (j << 3) + 4);
            float dv[8] = {da.x, da.y, da.z, da.w, db.x, db.y, db.z, db.w};
            #pragma unroll
            for (int h = 0; h < 8; h++) {
                const float ev = sh[h] + dv[h];
                const float lv = fmaxf(ev, 0.2f * ev);
                if (lv != 0.f) ws += __expf(lv) * rz8[h];
            }
        }
        s_off[w][lane] = off;
        s_wb[w][lane] = make_float2(ws, ws);
        __syncwarp();
        #pragma unroll
        for (int g = 0; g < 4; g++) {
            ull hpv[8];
            #pragma unroll
            for (int q = 0; q < 8; q++)
                hpv[q] = *(const ull*)(hpl + s_off[w][(g << 3) + q]);
            #pragma unroll
            for (int q = 0; q < 8; q++)
                acc = fma2(*(const ull*)&s_wb[w][(g << 3) + q], hpv[q], acc);
        }
        __syncwarp();
    }
    float xf, yf; upk2(acc, xf, yf);
    ((float2*)(out + ((size_t)row << 6)))[lane] = make_float2(xf, yf);
}

// ---------------- launch --------------------------------------------------------
extern "C" void kernel_launch(void* const* d_in, const int* in_sizes, int n_in,
                              void* d_out, int out_size) {
    const float* x     = (const float*)d_in[0];
    const float* adj   = (const float*)d_in[1];
    const float* W0    = (const float*)d_in[4];
    const float* asrc0 = (const float*)d_in[5];
    const float* adst0 = (const float*)d_in[6];
    const float* W1    = (const float*)d_in[7];
    const float* asrc1 = (const float*)d_in[8];
    const float* adst1 = (const float*)d_in[9];
    float* out = (float*)d_out;

    k_build_nbr<<<ROWS / 8, 256>>>(adj);
    k_gemm0<<<ROWS / 64, 256>>>(x, W0);
    k_sd<0><<<ROWS / 8, 256>>>(asrc0, adst0);
    k_agg1<<<ROWS / 4, 128>>>();
    k_gemm1<<<ROWS / 128, 256>>>(W1);
    k_sd<1><<<ROWS / 8, 256>>>(asrc1, adst1);
    k_agg2<<<ROWS / 4, 128>>>(out);
}

// round 9
// speedup vs baseline: 1.2128x; 1.0224x over previous
#include <cuda_runtime.h>
#include <cstdint>

#define BB 32
#define NN 512
#define FF 64
#define HH 8
#define ROWS (BB*NN)   // 16384

typedef unsigned long long ull;

// ---------------- scratch (static device globals; no allocation) ----------------
__device__ __align__(16) int16_t g_nbr[ROWS * NN];      // 16 MB neighbor lists
__device__              int      g_cnt[ROWS];
__device__ __align__(16) float   g_hp0[ROWS * FF];      // 4 MB
__device__ __align__(16) float   g_s0t[ROWS * HH];      // node-major [row][h]
__device__ __align__(16) float   g_d0t[ROWS * HH];
__device__ __align__(16) float   g_x1[ROWS * (HH*FF)];  // 32 MB (elu'd concat)
__device__ __align__(16) float   g_hp1[ROWS * FF];
__device__ __align__(16) float   g_s1t[ROWS * HH];
__device__ __align__(16) float   g_d1t[ROWS * HH];

// ---------------- packed f32x2 helpers ------------------------------------------
static __device__ __forceinline__ ull fma2(ull a, ull b, ull c) {
    ull r;
    asm("fma.rn.f32x2 %0, %1, %2, %3;" : "=l"(r) : "l"(a), "l"(b), "l"(c));
    return r;
}
static __device__ __forceinline__ ull mul2(ull a, ull b) {
    ull r;
    asm("mul.rn.f32x2 %0, %1, %2;" : "=l"(r) : "l"(a), "l"(b));
    return r;
}
static __device__ __forceinline__ ull pk2(float x, float y) {
    ull r;
    asm("mov.b64 %0, {%1, %2};" : "=l"(r) : "f"(x), "f"(y));
    return r;
}
static __device__ __forceinline__ void upk2(ull v, float& x, float& y) {
    asm("mov.b64 {%0, %1}, %2;" : "=f"(x), "=f"(y) : "l"(v));
}

// ---------------- kernel 1: compact adjacency rows into neighbor lists ----------
__global__ void __launch_bounds__(256) k_build_nbr(const float* __restrict__ adj) {
    const int row  = (blockIdx.x << 3) + (threadIdx.x >> 5);
    const int lane = threadIdx.x & 31;
    const int i    = row & (NN - 1);
    const float* arow = adj + ((size_t)row << 9);
    int16_t* outp = g_nbr + ((size_t)row << 9);
    int off = 0;
    #pragma unroll
    for (int base = 0; base < NN; base += 32) {
        const int j = base + lane;
        const bool p = (arow[j] != 0.f) || (j == i);   // diag forced to 1
        const unsigned msk = __ballot_sync(0xffffffffu, p);
        if (p) outp[off + __popc(msk & ((1u << lane) - 1u))] = (int16_t)j;
        off += __popc(msk);
    }
    if (lane == 0) g_cnt[row] = off;
}

// ---------------- kernel 2a: layer-0 GEMM  C[M,64] = A[M,64] @ B[64,64] ---------
__global__ void __launch_bounds__(256) k_gemm0(const float* __restrict__ A,
                                               const float* __restrict__ Bw) {
    float* __restrict__ C = g_hp0;
    __shared__ float As[32][72];   // As[kk][m] (transposed)
    __shared__ float Bs[32][72];   // Bs[kk][n]
    const int bm = blockIdx.x << 6;
    const int t  = threadIdx.x;
    const int ty = t >> 4, tx = t & 15;
    ull acc[4][2];
    #pragma unroll
    for (int r = 0; r < 4; r++) { acc[r][0] = 0ull; acc[r][1] = 0ull; }

    for (int k0 = 0; k0 < 64; k0 += 32) {
        #pragma unroll
        for (int l = 0; l < 2; l++) {
            const int idx = t + (l << 8);          // 0..511
            const int m  = idx >> 3;
            const int kq = (idx & 7) << 2;
            float4 av = *(const float4*)(A + (size_t)(bm + m) * 64 + k0 + kq);
            As[kq + 0][m] = av.x; As[kq + 1][m] = av.y;
            As[kq + 2][m] = av.z; As[kq + 3][m] = av.w;
            const int kk = idx >> 4;
            const int nq = (idx & 15) << 2;
            *(float4*)&Bs[kk][nq] = *(const float4*)(Bw + (size_t)(k0 + kk) * 64 + nq);
        }
        __syncthreads();
        #pragma unroll
        for (int kk = 0; kk < 32; kk++) {
            const float4 a = *(const float4*)&As[kk][ty << 2];
            const longlong2 bv = *(const longlong2*)&Bs[kk][tx << 2];
            const ull b0 = (ull)bv.x;
            const ull b1 = (ull)bv.y;
            const ull a0 = pk2(a.x, a.x), a1 = pk2(a.y, a.y);
            const ull a2 = pk2(a.z, a.z), a3 = pk2(a.w, a.w);
            acc[0][0] = fma2(a0, b0, acc[0][0]); acc[0][1] = fma2(a0, b1, acc[0][1]);
            acc[1][0] = fma2(a1, b0, acc[1][0]); acc[1][1] = fma2(a1, b1, acc[1][1]);
            acc[2][0] = fma2(a2, b0, acc[2][0]); acc[2][1] = fma2(a2, b1, acc[2][1]);
            acc[3][0] = fma2(a3, b0, acc[3][0]); acc[3][1] = fma2(a3, b1, acc[3][1]);
        }
        __syncthreads();
    }
    #pragma unroll
    for (int r = 0; r < 4; r++) {
        float o0, o1, o2, o3;
        upk2(acc[r][0], o0, o1); upk2(acc[r][1], o2, o3);
        *(float4*)(C + (size_t)(bm + (ty << 2) + r) * 64 + (tx << 2)) =
            make_float4(o0, o1, o2, o3);
    }
}

// ---------------- kernel 2b: layer-1 GEMM  C[M,64] = x1[M,512] @ W1[512,64] -----
// BM=128, BN=64, BK=32, 256 thr, 8x4 micro-tile.
__global__ void __launch_bounds__(256) k_gemm1(const float* __restrict__ Bw) {
    const float* __restrict__ A = g_x1;
    float* __restrict__ C = g_hp1;
    __shared__ float As[32][136];  // As[kk][m] (transposed), +8 pad
    __shared__ float Bs[32][72];
    const int bm = blockIdx.x << 7;
    const int t  = threadIdx.x;
    const int ty = t >> 4, tx = t & 15;   // ty: 8-row group, tx: 4-col group
    ull acc[8][2];
    #pragma unroll
    for (int r = 0; r < 8; r++) { acc[r][0] = 0ull; acc[r][1] = 0ull; }

    for (int k0 = 0; k0 < 512; k0 += 32) {
        #pragma unroll
        for (int l = 0; l < 4; l++) {
            const int idx = t + (l << 8);          // 0..1023 (float4 units)
            const int m  = idx >> 3;               // 0..127
            const int kq = (idx & 7) << 2;
            float4 av = *(const float4*)(A + (size_t)(bm + m) * 512 + k0 + kq);
            As[kq + 0][m] = av.x; As[kq + 1][m] = av.y;
            As[kq + 2][m] = av.z; As[kq + 3][m] = av.w;
        }
        #pragma unroll
        for (int l = 0; l < 2; l++) {
            const int idx = t + (l << 8);          // 0..511
            const int kk = idx >> 4;
            const int nq = (idx & 15) << 2;
            *(float4*)&Bs[kk][nq] = *(const float4*)(Bw + (size_t)(k0 + kk) * 64 + nq);
        }
        __syncthreads();
        #pragma unroll
        for (int kk = 0; kk < 32; kk++) {
            const float4 a0v = *(const float4*)&As[kk][ty << 3];
            const float4 a1v = *(const float4*)&As[kk][(ty << 3) + 4];
            const longlong2 bv = *(const longlong2*)&Bs[kk][tx << 2];
            const ull b0 = (ull)bv.x, b1 = (ull)bv.y;
            const float ar[8] = {a0v.x, a0v.y, a0v.z, a0v.w,
                                 a1v.x, a1v.y, a1v.z, a1v.w};
            #pragma unroll
            for (int r = 0; r < 8; r++) {
                const ull av2 = pk2(ar[r], ar[r]);
                acc[r][0] = fma2(av2, b0, acc[r][0]);
                acc[r][1] = fma2(av2, b1, acc[r][1]);
            }
        }
        __syncthreads();
    }
    #pragma unroll
    for (int r = 0; r < 8; r++) {
        float o0, o1, o2, o3;
        upk2(acc[r][0], o0, o1); upk2(acc[r][1], o2, o3);
        *(float4*)(C + (size_t)(bm + (ty << 3) + r) * 64 + (tx << 2)) =
            make_float4(o0, o1, o2, o3);
    }
}

// ---------------- kernel 3: s/d projections, stored NODE-MAJOR [row][h] ---------
template<int LAYER>
__global__ void __launch_bounds__(256) k_sd(const float* __restrict__ asrc,
                                            const float* __restrict__ adst) {
    const float* __restrict__ hp = (LAYER == 0) ? g_hp0 : g_hp1;
    float* __restrict__ s = (LAYER == 0) ? g_s0t : g_s1t;
    float* __restrict__ d = (LAYER == 0) ? g_d0t : g_d1t;
    const int row  = (blockIdx.x << 3) + (threadIdx.x >> 5);
    const int lane = threadIdx.x & 31;
    const float h0 = hp[(size_t)row * 64 + lane];
    const float h1 = hp[(size_t)row * 64 + 32 + lane];
    float ps[8], pd[8];
    #pragma unroll
    for (int h = 0; h < 8; h++) {
        ps[h] = h0 * asrc[(lane << 3) + h] + h1 * asrc[((lane + 32) << 3) + h];
        pd[h] = h0 * adst[(lane << 3) + h] + h1 * adst[((lane + 32) << 3) + h];
    }
    #pragma unroll
    for (int h = 0; h < 8; h++) {
        #pragma unroll
        for (int o = 16; o; o >>= 1) {
            ps[h] += __shfl_xor_sync(0xffffffffu, ps[h], o);
            pd[h] += __shfl_xor_sync(0xffffffffu, pd[h], o);
        }
    }
    if (lane == 0) {
        *(float4*)(s + (row << 3))     = make_float4(ps[0], ps[1], ps[2], ps[3]);
        *(float4*)(s + (row << 3) + 4) = make_float4(ps[4], ps[5], ps[6], ps[7]);
        *(float4*)(d + (row << 3))     = make_float4(pd[0], pd[1], pd[2], pd[3]);
        *(float4*)(d + (row << 3) + 4) = make_float4(pd[4], pd[5], pd[6], pd[7]);
    }
}

// ---------------- kernel 4: layer-1 one-pass aggregate, d[b] staged in SMEM -----
// All 4 warps of a CTA share one batch (4 | 512): load d[b] (16KB) to smem once.
__global__ void __launch_bounds__(128) k_agg1() {
    __shared__ __align__(16) float  s_d[NN * HH];    // 16KB: d[b] node-major
    __shared__ __align__(16) float2 s_w[4][32][8];   // chunk weights, pre-dup {w,w}
    __shared__ int s_off[4][32];                     // chunk hp byte offsets (j<<8)
    const int w = threadIdx.x >> 5, lane = threadIdx.x & 31;
    const int row = (blockIdx.x << 2) + w;
    const int b = row >> 9, i = row & (NN - 1);
    const int cnt = g_cnt[row];
    const int16_t* __restrict__ nbrrow = g_nbr + ((size_t)row << 9);
    const char*  __restrict__ hpl =
        (const char*)(g_hp0 + ((size_t)b << 15)) + (lane << 3);  // lane's 8B in row

    // cooperative load of d[b] into smem (1024 float4 / 128 threads = 8 each)
    {
        const float4* src = (const float4*)(g_d0t + ((size_t)b << 12));
        float4* dst = (float4*)s_d;
        #pragma unroll
        for (int t = 0; t < 8; t++)
            dst[threadIdx.x + (t << 7)] = src[threadIdx.x + (t << 7)];
    }
    __syncthreads();

    float sh[8], Zl[8];
    {
        const float4 s0 = *(const float4*)(g_s0t + (row << 3));
        const float4 s1 = *(const float4*)(g_s0t + (row << 3) + 4);
        sh[0] = s0.x; sh[1] = s0.y; sh[2] = s0.z; sh[3] = s0.w;
        sh[4] = s1.x; sh[5] = s1.y; sh[6] = s1.z; sh[7] = s1.w;
    }
    ull acc[8];
    #pragma unroll
    for (int h = 0; h < 8; h++) { Zl[h] = 0.f; acc[h] = 0ull; }

    for (int base = 0; base < cnt; base += 32) {
        const int nc = min(32, cnt - base);
        // weight phase: lane <-> neighbor; d from SMEM
        float wt[8];
        #pragma unroll
        for (int h = 0; h < 8; h++) wt[h] = 0.f;
        int off = i << 8;
        if (lane < nc) {
            const int j = (int)nbrrow[base + lane];
            off = j << 8;
            const float4 da = *(const float4*)(s_d + (j << 3));
            const float4 db = *(const float4*)(s_d + (j << 3) + 4);
            float dv[8] = {da.x, da.y, da.z, da.w, db.x, db.y, db.z, db.w};
            #pragma unroll
            for (int h = 0; h < 8; h++) {
                const float ev = sh[h] + dv[h];
                const float lv = fmaxf(ev, 0.2f * ev);
                const float e  = (lv != 0.f) ? __expf(lv) : 0.f;
                wt[h] = e;
                Zl[h] += e;
            }
        }
        s_off[w][lane] = off;
        {
            float4* wp = (float4*)&s_w[w][lane][0];
            wp[0] = make_float4(wt[0], wt[0], wt[1], wt[1]);
            wp[1] = make_float4(wt[2], wt[2], wt[3], wt[3]);
            wp[2] = make_float4(wt[4], wt[4], wt[5], wt[5]);
            wp[3] = make_float4(wt[6], wt[6], wt[7], wt[7]);
        }
        __syncwarp();
        // FMA phase: groups of 8 with batched loads (MLP=8), dynamic trip
        for (int g = 0; g < nc; g += 8) {
            ull hpv[8];
            #pragma unroll
            for (int q = 0; q < 8; q++)
                hpv[q] = *(const ull*)(hpl + s_off[w][g + q]);
            #pragma unroll
            for (int q = 0; q < 8; q++) {
                const longlong2* wp2 = (const longlong2*)&s_w[w][g + q][0];
                const longlong2 w01 = wp2[0], w23 = wp2[1];
                const longlong2 w45 = wp2[2], w67 = wp2[3];
                acc[0] = fma2((ull)w01.x, hpv[q], acc[0]);
                acc[1] = fma2((ull)w01.y, hpv[q], acc[1]);
                acc[2] = fma2((ull)w23.x, hpv[q], acc[2]);
                acc[3] = fma2((ull)w23.y, hpv[q], acc[3]);
                acc[4] = fma2((ull)w45.x, hpv[q], acc[4]);
                acc[5] = fma2((ull)w45.y, hpv[q], acc[5]);
                acc[6] = fma2((ull)w67.x, hpv[q], acc[6]);
                acc[7] = fma2((ull)w67.y, hpv[q], acc[7]);
            }
        }
        __syncwarp();
    }
    #pragma unroll
    for (int h = 0; h < 8; h++)
        #pragma unroll
        for (int o = 16; o; o >>= 1)
            Zl[h] += __shfl_xor_sync(0xffffffffu, Zl[h], o);
    float* xout = g_x1 + ((size_t)row << 9);
    #pragma unroll
    for (int h = 0; h < 8; h++) {
        const float rz = __fdividef(1.f, Zl[h]);
        float xf, yf; upk2(mul2(acc[h], pk2(rz, rz)), xf, yf);
        xf = xf > 0.f ? xf : (__expf(xf) - 1.f);
        yf = yf > 0.f ? yf : (__expf(yf) - 1.f);
        ((float2*)(xout + (h << 6)))[lane] = make_float2(xf, yf);
    }
}

// ---------------- kernel 5: layer-2 two-pass, d[b] staged in SMEM ---------------
__global__ void __launch_bounds__(128) k_agg2(float* __restrict__ out) {
    __shared__ __align__(16) float  s_d[NN * HH];    // 16KB
    __shared__ __align__(16) float2 s_wb[4][32];
    __shared__ int s_off[4][32];
    const int w = threadIdx.x >> 5, lane = threadIdx.x & 31;
    const int row = (blockIdx.x << 2) + w;
    const int b = row >> 9, i = row & (NN - 1);
    const int cnt = g_cnt[row];
    const int16_t* __restrict__ nbrrow = g_nbr + ((size_t)row << 9);
    const char*  __restrict__ hpl =
        (const char*)(g_hp1 + ((size_t)b << 15)) + (lane << 3);

    {
        const float4* src = (const float4*)(g_d1t + ((size_t)b << 12));
        float4* dst = (float4*)s_d;
        #pragma unroll
        for (int t = 0; t < 8; t++)
            dst[threadIdx.x + (t << 7)] = src[threadIdx.x + (t << 7)];
    }
    __syncthreads();

    float sh[8], Zl[8];
    {
        const float4 s0 = *(const float4*)(g_s1t + (row << 3));
        const float4 s1 = *(const float4*)(g_s1t + (row << 3) + 4);
        sh[0] = s0.x; sh[1] = s0.y; sh[2] = s0.z; sh[3] = s0.w;
        sh[4] = s1.x; sh[5] = s1.y; sh[6] = s1.z; sh[7] = s1.w;
    }
    #pragma unroll
    for (int h = 0; h < 8; h++) Zl[h] = 0.f;

    // pass 1: per-lane Z over strided neighbors (d from SMEM)
    #pragma unroll 2
    for (int p = lane; p < cnt; p += 32) {
        const int j = (int)nbrrow[p];
        const float4 da = *(const float4*)(s_d + (j << 3));
        const float4 db = *(const float4*)(s_d + (j << 3) + 4);
        float dv[8] = {da.x, da.y, da.z, da.w, db.x, db.y, db.z, db.w};
        #pragma unroll
        for (int h = 0; h < 8; h++) {
            const float ev = sh[h] + dv[h];
            const float lv = fmaxf(ev, 0.2f * ev);
            if (lv != 0.f) Zl[h] += __expf(lv);
        }
    }
    #pragma unroll
    for (int h = 0; h < 8; h++)
        #pragma unroll
        for (int o = 16; o; o >>= 1)
            Zl[h] += __shfl_xor_sync(0xffffffffu, Zl[h], o);
    float rz8[8];
    #pragma unroll
    for (int h = 0; h < 8; h++) rz8[h] = __fdividef(0.125f, Zl[h]);

    // pass 2: scalar weights (head-mean folded) + FMA
    ull acc = 0ull;
    for (int base = 0; base < cnt; base += 32) {
        const int nc = min(32, cnt - base);
        float ws = 0.f;
        int off = i << 8;
        if (lane < nc) {
            const int j = (int)nbrrow[base + lane];
            off = j << 8;
            const float4 da = *(const float4*)(s_d + (j << 3));
            const float4 db = *(const float4*)(s_d + (j << 3) + 4);
            float dv[8] = {da.x, da.y, da.z, da.w, db.x, db.y, db.z, db.w};
            #pragma unroll
            for (int h = 0; h < 8; h++) {
                const float ev = sh[h] + dv[h];
                const float lv = fmaxf(ev, 0.2f * ev);
                if (lv != 0.f) ws += __expf(lv) * rz8[h];
            }
        }
        s_off[w][lane] = off;
        s_wb[w][lane] = make_float2(ws, ws);
        __syncwarp();
        for (int g = 0; g < nc; g += 8) {
            ull hpv[8];
            #pragma unroll
            for (int q = 0; q < 8; q++)
                hpv[q] = *(const ull*)(hpl + s_off[w][g + q]);
            #pragma unroll
            for (int q = 0; q < 8; q++)
                acc = fma2(*(const ull*)&s_wb[w][g + q], hpv[q], acc);
        }
        __syncwarp();
    }
    float xf, yf; upk2(acc, xf, yf);
    ((float2*)(out + ((size_t)row << 6)))[lane] = make_float2(xf, yf);
}

// ---------------- launch --------------------------------------------------------
extern "C" void kernel_launch(void* const* d_in, const int* in_sizes, int n_in,
                              void* d_out, int out_size) {
    const float* x     = (const float*)d_in[0];
    const float* adj   = (const float*)d_in[1];
    const float* W0    = (const float*)d_in[4];
    const float* asrc0 = (const float*)d_in[5];
    const float* adst0 = (const float*)d_in[6];
    const float* W1    = (const float*)d_in[7];
    const float* asrc1 = (const float*)d_in[8];
    const float* adst1 = (const float*)d_in[9];
    float* out = (float*)d_out;

    k_build_nbr<<<ROWS / 8, 256>>>(adj);
    k_gemm0<<<ROWS / 64, 256>>>(x, W0);
    k_sd<0><<<ROWS / 8, 256>>>(asrc0, adst0);
    k_agg1<<<ROWS / 4, 128>>>();
    k_gemm1<<<ROWS / 128, 256>>>(W1);
    k_sd<1><<<ROWS / 8, 256>>>(asrc1, adst1);
    k_agg2<<<ROWS / 4, 128>>>(out);
}

// round 11
// speedup vs baseline: 1.3341x; 1.1000x over previous
#include <cuda_runtime.h>
#include <cstdint>

#define BB 32
#define NN 512
#define FF 64
#define HH 8
#define ROWS (BB*NN)   // 16384

typedef unsigned long long ull;

// ---------------- scratch (static device globals; no allocation) ----------------
__device__ __align__(16) int16_t g_nbr[ROWS * NN];      // 16 MB neighbor lists
__device__              int      g_cnt[ROWS];
__device__ __align__(16) float   g_hp0[ROWS * FF];      // 4 MB
__device__ __align__(16) float   g_s0t[ROWS * HH];      // node-major [row][h]
__device__ __align__(16) float   g_d0t[ROWS * HH];
__device__ __align__(16) float   g_x1[ROWS * (HH*FF)];  // 32 MB (elu'd concat)
__device__ __align__(16) float   g_hp1[ROWS * FF];
__device__ __align__(16) float   g_s1t[ROWS * HH];
__device__ __align__(16) float   g_d1t[ROWS * HH];

// ---------------- packed f32x2 helpers ------------------------------------------
static __device__ __forceinline__ ull fma2(ull a, ull b, ull c) {
    ull r;
    asm("fma.rn.f32x2 %0, %1, %2, %3;" : "=l"(r) : "l"(a), "l"(b), "l"(c));
    return r;
}
static __device__ __forceinline__ ull mul2(ull a, ull b) {
    ull r;
    asm("mul.rn.f32x2 %0, %1, %2;" : "=l"(r) : "l"(a), "l"(b));
    return r;
}
static __device__ __forceinline__ ull pk2(float x, float y) {
    ull r;
    asm("mov.b64 %0, {%1, %2};" : "=l"(r) : "f"(x), "f"(y));
    return r;
}
static __device__ __forceinline__ void upk2(ull v, float& x, float& y) {
    asm("mov.b64 {%0, %1}, %2;" : "=f"(x), "=f"(y) : "l"(v));
}

// ---------------- kernel 1: compact adjacency rows into neighbor lists ----------
__global__ void __launch_bounds__(256) k_build_nbr(const float* __restrict__ adj) {
    const int row  = (blockIdx.x << 3) + (threadIdx.x >> 5);
    const int lane = threadIdx.x & 31;
    const int i    = row & (NN - 1);
    const float* arow = adj + ((size_t)row << 9);
    int16_t* outp = g_nbr + ((size_t)row << 9);
    int off = 0;
    #pragma unroll
    for (int base = 0; base < NN; base += 32) {
        const int j = base + lane;
        const bool p = (arow[j] != 0.f) || (j == i);   // diag forced to 1
        const unsigned msk = __ballot_sync(0xffffffffu, p);
        if (p) outp[off + __popc(msk & ((1u << lane) - 1u))] = (int16_t)j;
        off += __popc(msk);
    }
    if (lane == 0) g_cnt[row] = off;
}

// ---------------- kernel 2a: layer-0 GEMM  C[M,64] = A[M,64] @ B[64,64] ---------
__global__ void __launch_bounds__(256) k_gemm0(const float* __restrict__ A,
                                               const float* __restrict__ Bw) {
    float* __restrict__ C = g_hp0;
    __shared__ float As[32][72];   // As[kk][m] (transposed)
    __shared__ float Bs[32][72];   // Bs[kk][n]
    const int bm = blockIdx.x << 6;
    const int t  = threadIdx.x;
    const int ty = t >> 4, tx = t & 15;
    ull acc[4][2];
    #pragma unroll
    for (int r = 0; r < 4; r++) { acc[r][0] = 0ull; acc[r][1] = 0ull; }

    for (int k0 = 0; k0 < 64; k0 += 32) {
        #pragma unroll
        for (int l = 0; l < 2; l++) {
            const int idx = t + (l << 8);          // 0..511
            const int m  = idx >> 3;
            const int kq = (idx & 7) << 2;
            float4 av = *(const float4*)(A + (size_t)(bm + m) * 64 + k0 + kq);
            As[kq + 0][m] = av.x; As[kq + 1][m] = av.y;
            As[kq + 2][m] = av.z; As[kq + 3][m] = av.w;
            const int kk = idx >> 4;
            const int nq = (idx & 15) << 2;
            *(float4*)&Bs[kk][nq] = *(const float4*)(Bw + (size_t)(k0 + kk) * 64 + nq);
        }
        __syncthreads();
        #pragma unroll
        for (int kk = 0; kk < 32; kk++) {
            const float4 a = *(const float4*)&As[kk][ty << 2];
            const longlong2 bv = *(const longlong2*)&Bs[kk][tx << 2];
            const ull b0 = (ull)bv.x;
            const ull b1 = (ull)bv.y;
            const ull a0 = pk2(a.x, a.x), a1 = pk2(a.y, a.y);
            const ull a2 = pk2(a.z, a.z), a3 = pk2(a.w, a.w);
            acc[0][0] = fma2(a0, b0, acc[0][0]); acc[0][1] = fma2(a0, b1, acc[0][1]);
            acc[1][0] = fma2(a1, b0, acc[1][0]); acc[1][1] = fma2(a1, b1, acc[1][1]);
            acc[2][0] = fma2(a2, b0, acc[2][0]); acc[2][1] = fma2(a2, b1, acc[2][1]);
            acc[3][0] = fma2(a3, b0, acc[3][0]); acc[3][1] = fma2(a3, b1, acc[3][1]);
        }
        __syncthreads();
    }
    #pragma unroll
    for (int r = 0; r < 4; r++) {
        float o0, o1, o2, o3;
        upk2(acc[r][0], o0, o1); upk2(acc[r][1], o2, o3);
        *(float4*)(C + (size_t)(bm + (ty << 2) + r) * 64 + (tx << 2)) =
            make_float4(o0, o1, o2, o3);
    }
}

// ---------------- kernel 2b: layer-1 GEMM  C[M,64] = x1[M,512] @ W1[512,64] -----
__global__ void __launch_bounds__(256) k_gemm1(const float* __restrict__ Bw) {
    const float* __restrict__ A = g_x1;
    float* __restrict__ C = g_hp1;
    __shared__ float As[32][136];  // As[kk][m] (transposed), +8 pad
    __shared__ float Bs[32][72];
    const int bm = blockIdx.x << 7;
    const int t  = threadIdx.x;
    const int ty = t >> 4, tx = t & 15;   // ty: 8-row group, tx: 4-col group
    ull acc[8][2];
    #pragma unroll
    for (int r = 0; r < 8; r++) { acc[r][0] = 0ull; acc[r][1] = 0ull; }

    for (int k0 = 0; k0 < 512; k0 += 32) {
        #pragma unroll
        for (int l = 0; l < 4; l++) {
            const int idx = t + (l << 8);          // 0..1023 (float4 units)
            const int m  = idx >> 3;               // 0..127
            const int kq = (idx & 7) << 2;
            float4 av = *(const float4*)(A + (size_t)(bm + m) * 512 + k0 + kq);
            As[kq + 0][m] = av.x; As[kq + 1][m] = av.y;
            As[kq + 2][m] = av.z; As[kq + 3][m] = av.w;
        }
        #pragma unroll
        for (int l = 0; l < 2; l++) {
            const int idx = t + (l << 8);          // 0..511
            const int kk = idx >> 4;
            const int nq = (idx & 15) << 2;
            *(float4*)&Bs[kk][nq] = *(const float4*)(Bw + (size_t)(k0 + kk) * 64 + nq);
        }
        __syncthreads();
        #pragma unroll
        for (int kk = 0; kk < 32; kk++) {
            const float4 a0v = *(const float4*)&As[kk][ty << 3];
            const float4 a1v = *(const float4*)&As[kk][(ty << 3) + 4];
            const longlong2 bv = *(const longlong2*)&Bs[kk][tx << 2];
            const ull b0 = (ull)bv.x, b1 = (ull)bv.y;
            const float ar[8] = {a0v.x, a0v.y, a0v.z, a0v.w,
                                 a1v.x, a1v.y, a1v.z, a1v.w};
            #pragma unroll
            for (int r = 0; r < 8; r++) {
                const ull av2 = pk2(ar[r], ar[r]);
                acc[r][0] = fma2(av2, b0, acc[r][0]);
                acc[r][1] = fma2(av2, b1, acc[r][1]);
            }
        }
        __syncthreads();
    }
    #pragma unroll
    for (int r = 0; r < 8; r++) {
        float o0, o1, o2, o3;
        upk2(acc[r][0], o0, o1); upk2(acc[r][1], o2, o3);
        *(float4*)(C + (size_t)(bm + (ty << 3) + r) * 64 + (tx << 2)) =
            make_float4(o0, o1, o2, o3);
    }
}

// ---------------- kernel 3: s/d projections, stored NODE-MAJOR [row][h] ---------
template<int LAYER>
__global__ void __launch_bounds__(256) k_sd(const float* __restrict__ asrc,
                                            const float* __restrict__ adst) {
    const float* __restrict__ hp = (LAYER == 0) ? g_hp0 : g_hp1;
    float* __restrict__ s = (LAYER == 0) ? g_s0t : g_s1t;
    float* __restrict__ d = (LAYER == 0) ? g_d0t : g_d1t;
    const int row  = (blockIdx.x << 3) + (threadIdx.x >> 5);
    const int lane = threadIdx.x & 31;
    const float h0 = hp[(size_t)row * 64 + lane];
    const float h1 = hp[(size_t)row * 64 + 32 + lane];
    float ps[8], pd[8];
    #pragma unroll
    for (int h = 0; h < 8; h++) {
        ps[h] = h0 * asrc[(lane << 3) + h] + h1 * asrc[((lane + 32) << 3) + h];
        pd[h] = h0 * adst[(lane << 3) + h] + h1 * adst[((lane + 32) << 3) + h];
    }
    #pragma unroll
    for (int h = 0; h < 8; h++) {
        #pragma unroll
        for (int o = 16; o; o >>= 1) {
            ps[h] += __shfl_xor_sync(0xffffffffu, ps[h], o);
            pd[h] += __shfl_xor_sync(0xffffffffu, pd[h], o);
        }
    }
    if (lane == 0) {
        *(float4*)(s + (row << 3))     = make_float4(ps[0], ps[1], ps[2], ps[3]);
        *(float4*)(s + (row << 3) + 4) = make_float4(ps[4], ps[5], ps[6], ps[7]);
        *(float4*)(d + (row << 3))     = make_float4(pd[0], pd[1], pd[2], pd[3]);
        *(float4*)(d + (row << 3) + 4) = make_float4(pd[4], pd[5], pd[6], pd[7]);
    }
}

// ---------------- kernel 4: layer-1 one-pass aggregate --------------------------
// d[b] staged in SMEM (split halves, 16B stride -> fewer bank conflicts).
// Weights stored UN-duplicated (32B/neighbor): FMA phase does 2 LDS.128 + 8 MOV
// packs instead of 4 LDS.128 broadcasts -> ~40% fewer L1 wavefronts.
__global__ void __launch_bounds__(128) k_agg1() {
    __shared__ __align__(16) float4 s_dA[NN], s_dB[NN];  // d[b][j][0:4], [4:8]
    __shared__ __align__(16) float  s_w[4][32][8];       // weights, un-duplicated
    __shared__ int s_off[4][32];                         // hp byte offsets (j<<8)
    const int w = threadIdx.x >> 5, lane = threadIdx.x & 31;
    const int row = (blockIdx.x << 2) + w;
    const int b = row >> 9, i = row & (NN - 1);
    const int cnt = g_cnt[row];
    const int16_t* __restrict__ nbrrow = g_nbr + ((size_t)row << 9);
    const char*  __restrict__ hpl =
        (const char*)(g_hp0 + ((size_t)b << 15)) + (lane << 3);  // lane's 8B in row

    // cooperative load of d[b]: 1024 float4 (even -> A, odd -> B)
    {
        const float4* src = (const float4*)(g_d0t + ((size_t)b << 12));
        #pragma unroll
        for (int t = 0; t < 8; t++) {
            const int e = threadIdx.x + (t << 7);   // 0..1023
            const float4 v = src[e];
            if (e & 1) s_dB[e >> 1] = v; else s_dA[e >> 1] = v;
        }
    }
    __syncthreads();

    float sh[8], Zl[8];
    {
        const float4 s0 = *(const float4*)(g_s0t + (row << 3));
        const float4 s1 = *(const float4*)(g_s0t + (row << 3) + 4);
        sh[0] = s0.x; sh[1] = s0.y; sh[2] = s0.z; sh[3] = s0.w;
        sh[4] = s1.x; sh[5] = s1.y; sh[6] = s1.z; sh[7] = s1.w;
    }
    ull acc[8];
    #pragma unroll
    for (int h = 0; h < 8; h++) { Zl[h] = 0.f; acc[h] = 0ull; }

    for (int base = 0; base < cnt; base += 32) {
        const int nc = min(32, cnt - base);
        // weight phase: lane <-> neighbor; d from split SMEM
        float wt[8];
        #pragma unroll
        for (int h = 0; h < 8; h++) wt[h] = 0.f;
        int off = i << 8;
        if (lane < nc) {
            const int j = (int)nbrrow[base + lane];
            off = j << 8;
            const float4 da = s_dA[j];
            const float4 db = s_dB[j];
            float dv[8] = {da.x, da.y, da.z, da.w, db.x, db.y, db.z, db.w};
            #pragma unroll
            for (int h = 0; h < 8; h++) {
                const float ev = sh[h] + dv[h];
                const float lv = fmaxf(ev, 0.2f * ev);
                const float e  = (lv != 0.f) ? __expf(lv) : 0.f;
                wt[h] = e;
                Zl[h] += e;
            }
        }
        s_off[w][lane] = off;
        {
            float4* wp = (float4*)&s_w[w][lane][0];
            wp[0] = make_float4(wt[0], wt[1], wt[2], wt[3]);
            wp[1] = make_float4(wt[4], wt[5], wt[6], wt[7]);
        }
        __syncwarp();
        // FMA phase: groups of 8 (MLP=8); weights re-packed from 2 LDS.128
        for (int g = 0; g < nc; g += 8) {
            ull hpv[8];
            #pragma unroll
            for (int q = 0; q < 8; q++)
                hpv[q] = *(const ull*)(hpl + s_off[w][g + q]);
            #pragma unroll
            for (int q = 0; q < 8; q++) {
                const float4 wa = *(const float4*)&s_w[w][g + q][0];
                const float4 wb = *(const float4*)&s_w[w][g + q][4];
                acc[0] = fma2(pk2(wa.x, wa.x), hpv[q], acc[0]);
                acc[1] = fma2(pk2(wa.y, wa.y), hpv[q], acc[1]);
                acc[2] = fma2(pk2(wa.z, wa.z), hpv[q], acc[2]);
                acc[3] = fma2(pk2(wa.w, wa.w), hpv[q], acc[3]);
                acc[4] = fma2(pk2(wb.x, wb.x), hpv[q], acc[4]);
                acc[5] = fma2(pk2(wb.y, wb.y), hpv[q], acc[5]);
                acc[6] = fma2(pk2(wb.z, wb.z), hpv[q], acc[6]);
                acc[7] = fma2(pk2(wb.w, wb.w), hpv[q], acc[7]);
            }
        }
        __syncwarp();
    }
    #pragma unroll
    for (int h = 0; h < 8; h++)
        #pragma unroll
        for (int o = 16; o; o >>= 1)
            Zl[h] += __shfl_xor_sync(0xffffffffu, Zl[h], o);
    float* xout = g_x1 + ((size_t)row << 9);
    #pragma unroll
    for (int h = 0; h < 8; h++) {
        const float rz = __fdividef(1.f, Zl[h]);
        float xf, yf; upk2(mul2(acc[h], pk2(rz, rz)), xf, yf);
        xf = xf > 0.f ? xf : (__expf(xf) - 1.f);
        yf = yf > 0.f ? yf : (__expf(yf) - 1.f);
        ((float2*)(xout + (h << 6)))[lane] = make_float2(xf, yf);
    }
}

// ---------------- kernel 5: layer-2 two-pass, d[b] staged (split) in SMEM -------
__global__ void __launch_bounds__(128) k_agg2(float* __restrict__ out) {
    __shared__ __align__(16) float4 s_dA[NN], s_dB[NN];
    __shared__ __align__(16) float  s_wb[4][32];
    __shared__ int s_off[4][32];
    const int w = threadIdx.x >> 5, lane = threadIdx.x & 31;
    const int row = (blockIdx.x << 2) + w;
    const int b = row >> 9, i = row & (NN - 1);
    const int cnt = g_cnt[row];
    const int16_t* __restrict__ nbrrow = g_nbr + ((size_t)row << 9);
    const char*  __restrict__ hpl =
        (const char*)(g_hp1 + ((size_t)b << 15)) + (lane << 3);

    {
        const float4* src = (const float4*)(g_d1t + ((size_t)b << 12));
        #pragma unroll
        for (int t = 0; t < 8; t++) {
            const int e = threadIdx.x + (t << 7);
            const float4 v = src[e];
            if (e & 1) s_dB[e >> 1] = v; else s_dA[e >> 1] = v;
        }
    }
    __syncthreads();

    float sh[8], Zl[8];
    {
        const float4 s0 = *(const float4*)(g_s1t + (row << 3));
        const float4 s1 = *(const float4*)(g_s1t + (row << 3) + 4);
        sh[0] = s0.x; sh[1] = s0.y; sh[2] = s0.z; sh[3] = s0.w;
        sh[4] = s1.x; sh[5] = s1.y; sh[6] = s1.z; sh[7] = s1.w;
    }
    #pragma unroll
    for (int h = 0; h < 8; h++) Zl[h] = 0.f;

    // pass 1: per-lane Z over strided neighbors
    #pragma unroll 2
    for (int p = lane; p < cnt; p += 32) {
        const int j = (int)nbrrow[p];
        const float4 da = s_dA[j];
        const float4 db = s_dB[j];
        float dv[8] = {da.x, da.y, da.z, da.w, db.x, db.y, db.z, db.w};
        #pragma unroll
        for (int h = 0; h < 8; h++) {
            const float ev = sh[h] + dv[h];
            const float lv = fmaxf(ev, 0.2f * ev);
            if (lv != 0.f) Zl[h] += __expf(lv);
        }
    }
    #pragma unroll
    for (int h = 0; h < 8; h++)
        #pragma unroll
        for (int o = 16; o; o >>= 1)
            Zl[h] += __shfl_xor_sync(0xffffffffu, Zl[h], o);
    float rz8[8];
    #pragma unroll
    for (int h = 0; h < 8; h++) rz8[h] = __fdividef(0.125f, Zl[h]);

    // pass 2: scalar weights (head-mean folded) + FMA
    ull acc = 0ull;
    for (int base = 0; base < cnt; base += 32) {
        const int nc = min(32, cnt - base);
        float ws = 0.f;
        int off = i << 8;
        if (lane < nc) {
            const int j = (int)nbrrow[base + lane];
            off = j << 8;
            const float4 da = s_dA[j];
            const float4 db = s_dB[j];
            float dv[8] = {da.x, da.y, da.z, da.w, db.x, db.y, db.z, db.w};
            #pragma unroll
            for (int h = 0; h < 8; h++) {
                const float ev = sh[h] + dv[h];
                const float lv = fmaxf(ev, 0.2f * ev);
                if (lv != 0.f) ws += __expf(lv) * rz8[h];
            }
        }
        s_off[w][lane] = off;
        s_wb[w][lane] = ws;
        __syncwarp();
        for (int g = 0; g < nc; g += 8) {
            ull hpv[8];
            #pragma unroll
            for (int q = 0; q < 8; q++)
                hpv[q] = *(const ull*)(hpl + s_off[w][g + q]);
            #pragma unroll
            for (int q = 0; q < 8; q++) {
                const float wv = s_wb[w][g + q];
                acc = fma2(pk2(wv, wv), hpv[q], acc);
            }
        }
        __syncwarp();
    }
    float xf, yf; upk2(acc, xf, yf);
    ((float2*)(out + ((size_t)row << 6)))[lane] = make_float2(xf, yf);
}

// ---------------- launch --------------------------------------------------------
extern "C" void kernel_launch(void* const* d_in, const int* in_sizes, int n_in,
                              void* d_out, int out_size) {
    const float* x     = (const float*)d_in[0];
    const float* adj   = (const float*)d_in[1];
    const float* W0    = (const float*)d_in[4];
    const float* asrc0 = (const float*)d_in[5];
    const float* adst0 = (const float*)d_in[6];
    const float* W1    = (const float*)d_in[7];
    const float* asrc1 = (const float*)d_in[8];
    const float* adst1 = (const float*)d_in[9];
    float* out = (float*)d_out;

    k_build_nbr<<<ROWS / 8, 256>>>(adj);
    k_gemm0<<<ROWS / 64, 256>>>(x, W0);
    k_sd<0><<<ROWS / 8, 256>>>(asrc0, adst0);
    k_agg1<<<ROWS / 4, 128>>>();
    k_gemm1<<<ROWS / 128, 256>>>(W1);
    k_sd<1><<<ROWS / 8, 256>>>(asrc1, adst1);
    k_agg2<<<ROWS / 4, 128>>>(out);
}

// round 12
// speedup vs baseline: 1.3505x; 1.0123x over previous
#include <cuda_runtime.h>
#include <cstdint>

#define BB 32
#define NN 512
#define FF 64
#define HH 8
#define ROWS (BB*NN)   // 16384

typedef unsigned long long ull;

// ---------------- scratch (static device globals; no allocation) ----------------
__device__ __align__(16) int16_t g_nbr[ROWS * NN];      // 16 MB neighbor lists
__device__              int      g_cnt[ROWS];
__device__ __align__(16) float   g_hp0[ROWS * FF];      // 4 MB
__device__ __align__(16) float   g_s0t[ROWS * HH];      // node-major [row][h]
__device__ __align__(16) float   g_d0t[ROWS * HH];
__device__ __align__(16) float   g_x1[ROWS * (HH*FF)];  // 32 MB (elu'd concat)
__device__ __align__(16) float   g_hp1[ROWS * FF];
__device__ __align__(16) float   g_s1t[ROWS * HH];
__device__ __align__(16) float   g_d1t[ROWS * HH];

// ---------------- packed f32x2 helpers ------------------------------------------
static __device__ __forceinline__ ull fma2(ull a, ull b, ull c) {
    ull r;
    asm("fma.rn.f32x2 %0, %1, %2, %3;" : "=l"(r) : "l"(a), "l"(b), "l"(c));
    return r;
}
static __device__ __forceinline__ ull mul2(ull a, ull b) {
    ull r;
    asm("mul.rn.f32x2 %0, %1, %2;" : "=l"(r) : "l"(a), "l"(b));
    return r;
}
static __device__ __forceinline__ ull pk2(float x, float y) {
    ull r;
    asm("mov.b64 %0, {%1, %2};" : "=l"(r) : "f"(x), "f"(y));
    return r;
}
static __device__ __forceinline__ void upk2(ull v, float& x, float& y) {
    asm("mov.b64 {%0, %1}, %2;" : "=f"(x), "=f"(y) : "l"(v));
}

// ---------------- kernel 1: compact adjacency rows into neighbor lists ----------
__global__ void __launch_bounds__(256) k_build_nbr(const float* __restrict__ adj) {
    const int row  = (blockIdx.x << 3) + (threadIdx.x >> 5);
    const int lane = threadIdx.x & 31;
    const int i    = row & (NN - 1);
    const float* arow = adj + ((size_t)row << 9);
    int16_t* outp = g_nbr + ((size_t)row << 9);
    int off = 0;
    #pragma unroll
    for (int base = 0; base < NN; base += 32) {
        const int j = base + lane;
        const bool p = (arow[j] != 0.f) || (j == i);   // diag forced to 1
        const unsigned msk = __ballot_sync(0xffffffffu, p);
        if (p) outp[off + __popc(msk & ((1u << lane) - 1u))] = (int16_t)j;
        off += __popc(msk);
    }
    if (lane == 0) g_cnt[row] = off;
}

// ---------------- kernel 2a: layer-0 GEMM  C[M,64] = A[M,64] @ B[64,64] ---------
__global__ void __launch_bounds__(256) k_gemm0(const float* __restrict__ A,
                                               const float* __restrict__ Bw) {
    float* __restrict__ C = g_hp0;
    __shared__ float As[32][72];   // As[kk][m] (transposed)
    __shared__ float Bs[32][72];   // Bs[kk][n]
    const int bm = blockIdx.x << 6;
    const int t  = threadIdx.x;
    const int ty = t >> 4, tx = t & 15;
    ull acc[4][2];
    #pragma unroll
    for (int r = 0; r < 4; r++) { acc[r][0] = 0ull; acc[r][1] = 0ull; }

    for (int k0 = 0; k0 < 64; k0 += 32) {
        #pragma unroll
        for (int l = 0; l < 2; l++) {
            const int idx = t + (l << 8);          // 0..511
            const int m  = idx >> 3;
            const int kq = (idx & 7) << 2;
            float4 av = *(const float4*)(A + (size_t)(bm + m) * 64 + k0 + kq);
            As[kq + 0][m] = av.x; As[kq + 1][m] = av.y;
            As[kq + 2][m] = av.z; As[kq + 3][m] = av.w;
            const int kk = idx >> 4;
            const int nq = (idx & 15) << 2;
            *(float4*)&Bs[kk][nq] = *(const float4*)(Bw + (size_t)(k0 + kk) * 64 + nq);
        }
        __syncthreads();
        #pragma unroll
        for (int kk = 0; kk < 32; kk++) {
            const float4 a = *(const float4*)&As[kk][ty << 2];
            const longlong2 bv = *(const longlong2*)&Bs[kk][tx << 2];
            const ull b0 = (ull)bv.x;
            const ull b1 = (ull)bv.y;
            const ull a0 = pk2(a.x, a.x), a1 = pk2(a.y, a.y);
            const ull a2 = pk2(a.z, a.z), a3 = pk2(a.w, a.w);
            acc[0][0] = fma2(a0, b0, acc[0][0]); acc[0][1] = fma2(a0, b1, acc[0][1]);
            acc[1][0] = fma2(a1, b0, acc[1][0]); acc[1][1] = fma2(a1, b1, acc[1][1]);
            acc[2][0] = fma2(a2, b0, acc[2][0]); acc[2][1] = fma2(a2, b1, acc[2][1]);
            acc[3][0] = fma2(a3, b0, acc[3][0]); acc[3][1] = fma2(a3, b1, acc[3][1]);
        }
        __syncthreads();
    }
    #pragma unroll
    for (int r = 0; r < 4; r++) {
        float o0, o1, o2, o3;
        upk2(acc[r][0], o0, o1); upk2(acc[r][1], o2, o3);
        *(float4*)(C + (size_t)(bm + (ty << 2) + r) * 64 + (tx << 2)) =
            make_float4(o0, o1, o2, o3);
    }
}

// ---------------- kernel 2b: layer-1 GEMM  C[M,64] = x1[M,512] @ W1[512,64] -----
__global__ void __launch_bounds__(256) k_gemm1(const float* __restrict__ Bw) {
    const float* __restrict__ A = g_x1;
    float* __restrict__ C = g_hp1;
    __shared__ float As[32][136];  // As[kk][m] (transposed), +8 pad
    __shared__ float Bs[32][72];
    const int bm = blockIdx.x << 7;
    const int t  = threadIdx.x;
    const int ty = t >> 4, tx = t & 15;   // ty: 8-row group, tx: 4-col group
    ull acc[8][2];
    #pragma unroll
    for (int r = 0; r < 8; r++) { acc[r][0] = 0ull; acc[r][1] = 0ull; }

    for (int k0 = 0; k0 < 512; k0 += 32) {
        #pragma unroll
        for (int l = 0; l < 4; l++) {
            const int idx = t + (l << 8);          // 0..1023 (float4 units)
            const int m  = idx >> 3;               // 0..127
            const int kq = (idx & 7) << 2;
            float4 av = *(const float4*)(A + (size_t)(bm + m) * 512 + k0 + kq);
            As[kq + 0][m] = av.x; As[kq + 1][m] = av.y;
            As[kq + 2][m] = av.z; As[kq + 3][m] = av.w;
        }
        #pragma unroll
        for (int l = 0; l < 2; l++) {
            const int idx = t + (l << 8);          // 0..511
            const int kk = idx >> 4;
            const int nq = (idx & 15) << 2;
            *(float4*)&Bs[kk][nq] = *(const float4*)(Bw + (size_t)(k0 + kk) * 64 + nq);
        }
        __syncthreads();
        #pragma unroll
        for (int kk = 0; kk < 32; kk++) {
            const float4 a0v = *(const float4*)&As[kk][ty << 3];
            const float4 a1v = *(const float4*)&As[kk][(ty << 3) + 4];
            const longlong2 bv = *(const longlong2*)&Bs[kk][tx << 2];
            const ull b0 = (ull)bv.x, b1 = (ull)bv.y;
            const float ar[8] = {a0v.x, a0v.y, a0v.z, a0v.w,
                                 a1v.x, a1v.y, a1v.z, a1v.w};
            #pragma unroll
            for (int r = 0; r < 8; r++) {
                const ull av2 = pk2(ar[r], ar[r]);
                acc[r][0] = fma2(av2, b0, acc[r][0]);
                acc[r][1] = fma2(av2, b1, acc[r][1]);
            }
        }
        __syncthreads();
    }
    #pragma unroll
    for (int r = 0; r < 8; r++) {
        float o0, o1, o2, o3;
        upk2(acc[r][0], o0, o1); upk2(acc[r][1], o2, o3);
        *(float4*)(C + (size_t)(bm + (ty << 3) + r) * 64 + (tx << 2)) =
            make_float4(o0, o1, o2, o3);
    }
}

// ---------------- kernel 3: s/d projections, stored NODE-MAJOR [row][h] ---------
template<int LAYER>
__global__ void __launch_bounds__(256) k_sd(const float* __restrict__ asrc,
                                            const float* __restrict__ adst) {
    const float* __restrict__ hp = (LAYER == 0) ? g_hp0 : g_hp1;
    float* __restrict__ s = (LAYER == 0) ? g_s0t : g_s1t;
    float* __restrict__ d = (LAYER == 0) ? g_d0t : g_d1t;
    const int row  = (blockIdx.x << 3) + (threadIdx.x >> 5);
    const int lane = threadIdx.x & 31;
    const float h0 = hp[(size_t)row * 64 + lane];
    const float h1 = hp[(size_t)row * 64 + 32 + lane];
    float ps[8], pd[8];
    #pragma unroll
    for (int h = 0; h < 8; h++) {
        ps[h] = h0 * asrc[(lane << 3) + h] + h1 * asrc[((lane + 32) << 3) + h];
        pd[h] = h0 * adst[(lane << 3) + h] + h1 * adst[((lane + 32) << 3) + h];
    }
    #pragma unroll
    for (int h = 0; h < 8; h++) {
        #pragma unroll
        for (int o = 16; o; o >>= 1) {
            ps[h] += __shfl_xor_sync(0xffffffffu, ps[h], o);
            pd[h] += __shfl_xor_sync(0xffffffffu, pd[h], o);
        }
    }
    if (lane == 0) {
        *(float4*)(s + (row << 3))     = make_float4(ps[0], ps[1], ps[2], ps[3]);
        *(float4*)(s + (row << 3) + 4) = make_float4(ps[4], ps[5], ps[6], ps[7]);
        *(float4*)(d + (row << 3))     = make_float4(pd[0], pd[1], pd[2], pd[3]);
        *(float4*)(d + (row << 3) + 4) = make_float4(pd[4], pd[5], pd[6], pd[7]);
    }
}

// ---------------- kernel 4: layer-1 one-pass aggregate --------------------------
// d[b] staged in SMEM (split halves); weights un-duplicated (re-packed via MOV);
// offsets read as int4 broadcasts; regs capped for 8 CTAs/SM.
__global__ void __launch_bounds__(128, 8) k_agg1() {
    __shared__ __align__(16) float4 s_dA[NN], s_dB[NN];  // d[b][j][0:4], [4:8]
    __shared__ __align__(16) float  s_w[4][32][8];       // weights, un-duplicated
    __shared__ __align__(16) int    s_off[4][32];        // hp byte offsets (j<<8)
    const int w = threadIdx.x >> 5, lane = threadIdx.x & 31;
    const int row = (blockIdx.x << 2) + w;
    const int b = row >> 9, i = row & (NN - 1);
    const int cnt = g_cnt[row];
    const int16_t* __restrict__ nbrrow = g_nbr + ((size_t)row << 9);
    const char*  __restrict__ hpl =
        (const char*)(g_hp0 + ((size_t)b << 15)) + (lane << 3);  // lane's 8B in row

    // cooperative load of d[b]: 1024 float4 (even -> A, odd -> B)
    {
        const float4* src = (const float4*)(g_d0t + ((size_t)b << 12));
        #pragma unroll
        for (int t = 0; t < 8; t++) {
            const int e = threadIdx.x + (t << 7);   // 0..1023
            const float4 v = src[e];
            if (e & 1) s_dB[e >> 1] = v; else s_dA[e >> 1] = v;
        }
    }
    __syncthreads();

    float sh[8], Zl[8];
    {
        const float4 s0 = *(const float4*)(g_s0t + (row << 3));
        const float4 s1 = *(const float4*)(g_s0t + (row << 3) + 4);
        sh[0] = s0.x; sh[1] = s0.y; sh[2] = s0.z; sh[3] = s0.w;
        sh[4] = s1.x; sh[5] = s1.y; sh[6] = s1.z; sh[7] = s1.w;
    }
    ull acc[8];
    #pragma unroll
    for (int h = 0; h < 8; h++) { Zl[h] = 0.f; acc[h] = 0ull; }

    for (int base = 0; base < cnt; base += 32) {
        const int nc = min(32, cnt - base);
        // weight phase: lane <-> neighbor; d from split SMEM
        float wt[8];
        #pragma unroll
        for (int h = 0; h < 8; h++) wt[h] = 0.f;
        int off = i << 8;
        if (lane < nc) {
            const int j = (int)nbrrow[base + lane];
            off = j << 8;
            const float4 da = s_dA[j];
            const float4 db = s_dB[j];
            float dv[8] = {da.x, da.y, da.z, da.w, db.x, db.y, db.z, db.w};
            #pragma unroll
            for (int h = 0; h < 8; h++) {
                const float ev = sh[h] + dv[h];
                const float lv = fmaxf(ev, 0.2f * ev);
                const float e  = (lv != 0.f) ? __expf(lv) : 0.f;
                wt[h] = e;
                Zl[h] += e;
            }
        }
        s_off[w][lane] = off;
        {
            float4* wp = (float4*)&s_w[w][lane][0];
            wp[0] = make_float4(wt[0], wt[1], wt[2], wt[3]);
            wp[1] = make_float4(wt[4], wt[5], wt[6], wt[7]);
        }
        __syncwarp();
        // FMA phase: groups of 8 (MLP=8); offsets via int4 broadcasts
        for (int g = 0; g < nc; g += 8) {
            const int4 of0 = *(const int4*)&s_off[w][g];
            const int4 of1 = *(const int4*)&s_off[w][g + 4];
            ull hpv[8];
            hpv[0] = *(const ull*)(hpl + of0.x);
            hpv[1] = *(const ull*)(hpl + of0.y);
            hpv[2] = *(const ull*)(hpl + of0.z);
            hpv[3] = *(const ull*)(hpl + of0.w);
            hpv[4] = *(const ull*)(hpl + of1.x);
            hpv[5] = *(const ull*)(hpl + of1.y);
            hpv[6] = *(const ull*)(hpl + of1.z);
            hpv[7] = *(const ull*)(hpl + of1.w);
            #pragma unroll
            for (int q = 0; q < 8; q++) {
                const float4 wa = *(const float4*)&s_w[w][g + q][0];
                const float4 wb = *(const float4*)&s_w[w][g + q][4];
                acc[0] = fma2(pk2(wa.x, wa.x), hpv[q], acc[0]);
                acc[1] = fma2(pk2(wa.y, wa.y), hpv[q], acc[1]);
                acc[2] = fma2(pk2(wa.z, wa.z), hpv[q], acc[2]);
                acc[3] = fma2(pk2(wa.w, wa.w), hpv[q], acc[3]);
                acc[4] = fma2(pk2(wb.x, wb.x), hpv[q], acc[4]);
                acc[5] = fma2(pk2(wb.y, wb.y), hpv[q], acc[5]);
                acc[6] = fma2(pk2(wb.z, wb.z), hpv[q], acc[6]);
                acc[7] = fma2(pk2(wb.w, wb.w), hpv[q], acc[7]);
            }
        }
        __syncwarp();
    }
    #pragma unroll
    for (int h = 0; h < 8; h++)
        #pragma unroll
        for (int o = 16; o; o >>= 1)
            Zl[h] += __shfl_xor_sync(0xffffffffu, Zl[h], o);
    float* xout = g_x1 + ((size_t)row << 9);
    #pragma unroll
    for (int h = 0; h < 8; h++) {
        const float rz = __fdividef(1.f, Zl[h]);
        float xf, yf; upk2(mul2(acc[h], pk2(rz, rz)), xf, yf);
        xf = xf > 0.f ? xf : (__expf(xf) - 1.f);
        yf = yf > 0.f ? yf : (__expf(yf) - 1.f);
        ((float2*)(xout + (h << 6)))[lane] = make_float2(xf, yf);
    }
}

// ---------------- kernel 5: layer-2 two-pass, d[b] staged (split) in SMEM -------
__global__ void __launch_bounds__(128, 8) k_agg2(float* __restrict__ out) {
    __shared__ __align__(16) float4 s_dA[NN], s_dB[NN];
    __shared__ __align__(16) float  s_wb[4][32];
    __shared__ __align__(16) int    s_off[4][32];
    const int w = threadIdx.x >> 5, lane = threadIdx.x & 31;
    const int row = (blockIdx.x << 2) + w;
    const int b = row >> 9, i = row & (NN - 1);
    const int cnt = g_cnt[row];
    const int16_t* __restrict__ nbrrow = g_nbr + ((size_t)row << 9);
    const char*  __restrict__ hpl =
        (const char*)(g_hp1 + ((size_t)b << 15)) + (lane << 3);

    {
        const float4* src = (const float4*)(g_d1t + ((size_t)b << 12));
        #pragma unroll
        for (int t = 0; t < 8; t++) {
            const int e = threadIdx.x + (t << 7);
            const float4 v = src[e];
            if (e & 1) s_dB[e >> 1] = v; else s_dA[e >> 1] = v;
        }
    }
    __syncthreads();

    float sh[8], Zl[8];
    {
        const float4 s0 = *(const float4*)(g_s1t + (row << 3));
        const float4 s1 = *(const float4*)(g_s1t + (row << 3) + 4);
        sh[0] = s0.x; sh[1] = s0.y; sh[2] = s0.z; sh[3] = s0.w;
        sh[4] = s1.x; sh[5] = s1.y; sh[6] = s1.z; sh[7] = s1.w;
    }
    #pragma unroll
    for (int h = 0; h < 8; h++) Zl[h] = 0.f;

    // pass 1: per-lane Z over strided neighbors
    #pragma unroll 2
    for (int p = lane; p < cnt; p += 32) {
        const int j = (int)nbrrow[p];
        const float4 da = s_dA[j];
        const float4 db = s_dB[j];
        float dv[8] = {da.x, da.y, da.z, da.w, db.x, db.y, db.z, db.w};
        #pragma unroll
        for (int h = 0; h < 8; h++) {
            const float ev = sh[h] + dv[h];
            const float lv = fmaxf(ev, 0.2f * ev);
            if (lv != 0.f) Zl[h] += __expf(lv);
        }
    }
    #pragma unroll
    for (int h = 0; h < 8; h++)
        #pragma unroll
        for (int o = 16; o; o >>= 1)
            Zl[h] += __shfl_xor_sync(0xffffffffu, Zl[h], o);
    float rz8[8];
    #pragma unroll
    for (int h = 0; h < 8; h++) rz8[h] = __fdividef(0.125f, Zl[h]);

    // pass 2: scalar weights (head-mean folded) + FMA
    ull acc = 0ull;
    for (int base = 0; base < cnt; base += 32) {
        const int nc = min(32, cnt - base);
        float ws = 0.f;
        int off = i << 8;
        if (lane < nc) {
            const int j = (int)nbrrow[base + lane];
            off = j << 8;
            const float4 da = s_dA[j];
            const float4 db = s_dB[j];
            float dv[8] = {da.x, da.y, da.z, da.w, db.x, db.y, db.z, db.w};
            #pragma unroll
            for (int h = 0; h < 8; h++) {
                const float ev = sh[h] + dv[h];
                const float lv = fmaxf(ev, 0.2f * ev);
                if (lv != 0.f) ws += __expf(lv) * rz8[h];
            }
        }
        s_off[w][lane] = off;
        s_wb[w][lane] = ws;
        __syncwarp();
        for (int g = 0; g < nc; g += 8) {
            const int4 of0 = *(const int4*)&s_off[w][g];
            const int4 of1 = *(const int4*)&s_off[w][g + 4];
            const float4 wv0 = *(const float4*)&s_wb[w][g];
            const float4 wv1 = *(const float4*)&s_wb[w][g + 4];
            ull hpv[8];
            hpv[0] = *(const ull*)(hpl + of0.x);
            hpv[1] = *(const ull*)(hpl + of0.y);
            hpv[2] = *(const ull*)(hpl + of0.z);
            hpv[3] = *(const ull*)(hpl + of0.w);
            hpv[4] = *(const ull*)(hpl + of1.x);
            hpv[5] = *(const ull*)(hpl + of1.y);
            hpv[6] = *(const ull*)(hpl + of1.z);
            hpv[7] = *(const ull*)(hpl + of1.w);
            acc = fma2(pk2(wv0.x, wv0.x), hpv[0], acc);
            acc = fma2(pk2(wv0.y, wv0.y), hpv[1], acc);
            acc = fma2(pk2(wv0.z, wv0.z), hpv[2], acc);
            acc = fma2(pk2(wv0.w, wv0.w), hpv[3], acc);
            acc = fma2(pk2(wv1.x, wv1.x), hpv[4], acc);
            acc = fma2(pk2(wv1.y, wv1.y), hpv[5], acc);
            acc = fma2(pk2(wv1.z, wv1.z), hpv[6], acc);
            acc = fma2(pk2(wv1.w, wv1.w), hpv[7], acc);
        }
        __syncwarp();
    }
    float xf, yf; upk2(acc, xf, yf);
    ((float2*)(out + ((size_t)row << 6)))[lane] = make_float2(xf, yf);
}

// ---------------- launch --------------------------------------------------------
extern "C" void kernel_launch(void* const* d_in, const int* in_sizes, int n_in,
                              void* d_out, int out_size) {
    const float* x     = (const float*)d_in[0];
    const float* adj   = (const float*)d_in[1];
    const float* W0    = (const float*)d_in[4];
    const float* asrc0 = (const float*)d_in[5];
    const float* adst0 = (const float*)d_in[6];
    const float* W1    = (const float*)d_in[7];
    const float* asrc1 = (const float*)d_in[8];
    const float* adst1 = (const float*)d_in[9];
    float* out = (float*)d_out;

    k_build_nbr<<<ROWS / 8, 256>>>(adj);
    k_gemm0<<<ROWS / 64, 256>>>(x, W0);
    k_sd<0><<<ROWS / 8, 256>>>(asrc0, adst0);
    k_agg1<<<ROWS / 4, 128>>>();
    k_gemm1<<<ROWS / 128, 256>>>(W1);
    k_sd<1><<<ROWS / 8, 256>>>(asrc1, adst1);
    k_agg2<<<ROWS / 4, 128>>>(out);
}

// round 13
// speedup vs baseline: 1.3507x; 1.0002x over previous
#include <cuda_runtime.h>
#include <cstdint>

#define BB 32
#define NN 512
#define FF 64
#define HH 8
#define ROWS (BB*NN)   // 16384

typedef unsigned long long ull;

// ---------------- scratch (static device globals; no allocation) ----------------
__device__ __align__(16) int16_t g_nbr[ROWS * NN];      // 16 MB neighbor lists
__device__              int      g_cnt[ROWS];
__device__ __align__(16) float   g_hp0[ROWS * FF];      // 4 MB
__device__ __align__(16) float   g_s0t[ROWS * HH];      // node-major [row][h]
__device__ __align__(16) float   g_d0t[ROWS * HH];
__device__ __align__(16) float   g_x1[ROWS * (HH*FF)];  // 32 MB (elu'd concat)
__device__ __align__(16) float   g_hp1[ROWS * FF];
__device__ __align__(16) float   g_s1t[ROWS * HH];
__device__ __align__(16) float   g_d1t[ROWS * HH];

// ---------------- packed f32x2 helpers ------------------------------------------
static __device__ __forceinline__ ull fma2(ull a, ull b, ull c) {
    ull r;
    asm("fma.rn.f32x2 %0, %1, %2, %3;" : "=l"(r) : "l"(a), "l"(b), "l"(c));
    return r;
}
static __device__ __forceinline__ ull mul2(ull a, ull b) {
    ull r;
    asm("mul.rn.f32x2 %0, %1, %2;" : "=l"(r) : "l"(a), "l"(b));
    return r;
}
static __device__ __forceinline__ ull pk2(float x, float y) {
    ull r;
    asm("mov.b64 %0, {%1, %2};" : "=l"(r) : "f"(x), "f"(y));
    return r;
}
static __device__ __forceinline__ void upk2(ull v, float& x, float& y) {
    asm("mov.b64 {%0, %1}, %2;" : "=f"(x), "=f"(y) : "l"(v));
}

// ---------------- kernel 1: compact adjacency rows into neighbor lists ----------
__global__ void __launch_bounds__(256) k_build_nbr(const float* __restrict__ adj) {
    const int row  = (blockIdx.x << 3) + (threadIdx.x >> 5);
    const int lane = threadIdx.x & 31;
    const int i    = row & (NN - 1);
    const float* arow = adj + ((size_t)row << 9);
    int16_t* outp = g_nbr + ((size_t)row << 9);
    int off = 0;
    #pragma unroll
    for (int base = 0; base < NN; base += 32) {
        const int j = base + lane;
        const bool p = (arow[j] != 0.f) || (j == i);   // diag forced to 1
        const unsigned msk = __ballot_sync(0xffffffffu, p);
        if (p) outp[off + __popc(msk & ((1u << lane) - 1u))] = (int16_t)j;
        off += __popc(msk);
    }
    if (lane == 0) g_cnt[row] = off;
}

// ---------------- kernel 2a: layer-0 GEMM  C[M,64] = A[M,64] @ B[64,64] ---------
__global__ void __launch_bounds__(256) k_gemm0(const float* __restrict__ A,
                                               const float* __restrict__ Bw) {
    float* __restrict__ C = g_hp0;
    __shared__ float As[32][72];   // As[kk][m] (transposed)
    __shared__ float Bs[32][72];   // Bs[kk][n]
    const int bm = blockIdx.x << 6;
    const int t  = threadIdx.x;
    const int ty = t >> 4, tx = t & 15;
    ull acc[4][2];
    #pragma unroll
    for (int r = 0; r < 4; r++) { acc[r][0] = 0ull; acc[r][1] = 0ull; }

    for (int k0 = 0; k0 < 64; k0 += 32) {
        #pragma unroll
        for (int l = 0; l < 2; l++) {
            const int idx = t + (l << 8);          // 0..511
            const int m  = idx >> 3;
            const int kq = (idx & 7) << 2;
            float4 av = *(const float4*)(A + (size_t)(bm + m) * 64 + k0 + kq);
            As[kq + 0][m] = av.x; As[kq + 1][m] = av.y;
            As[kq + 2][m] = av.z; As[kq + 3][m] = av.w;
            const int kk = idx >> 4;
            const int nq = (idx & 15) << 2;
            *(float4*)&Bs[kk][nq] = *(const float4*)(Bw + (size_t)(k0 + kk) * 64 + nq);
        }
        __syncthreads();
        #pragma unroll
        for (int kk = 0; kk < 32; kk++) {
            const float4 a = *(const float4*)&As[kk][ty << 2];
            const longlong2 bv = *(const longlong2*)&Bs[kk][tx << 2];
            const ull b0 = (ull)bv.x;
            const ull b1 = (ull)bv.y;
            const ull a0 = pk2(a.x, a.x), a1 = pk2(a.y, a.y);
            const ull a2 = pk2(a.z, a.z), a3 = pk2(a.w, a.w);
            acc[0][0] = fma2(a0, b0, acc[0][0]); acc[0][1] = fma2(a0, b1, acc[0][1]);
            acc[1][0] = fma2(a1, b0, acc[1][0]); acc[1][1] = fma2(a1, b1, acc[1][1]);
            acc[2][0] = fma2(a2, b0, acc[2][0]); acc[2][1] = fma2(a2, b1, acc[2][1]);
            acc[3][0] = fma2(a3, b0, acc[3][0]); acc[3][1] = fma2(a3, b1, acc[3][1]);
        }
        __syncthreads();
    }
    #pragma unroll
    for (int r = 0; r < 4; r++) {
        float o0, o1, o2, o3;
        upk2(acc[r][0], o0, o1); upk2(acc[r][1], o2, o3);
        *(float4*)(C + (size_t)(bm + (ty << 2) + r) * 64 + (tx << 2)) =
            make_float4(o0, o1, o2, o3);
    }
}

// ---------------- kernel 2b: layer-1 GEMM  C[M,64] = x1[M,512] @ W1[512,64] -----
// BM=128, BN=64, BK=16, double-buffered smem, m-pair micro-tile (a packed, b
// splatted: 8 MOVs/kk instead of 16). 256 thr; grid = 128 CTAs (1/SM).
__global__ void __launch_bounds__(256) k_gemm1(const float* __restrict__ Bw) {
    const float* __restrict__ A = g_x1;
    float* __restrict__ C = g_hp1;
    __shared__ float As[2][16][132];  // [buf][kk][m], stride 132 (16B-aligned)
    __shared__ float Bs[2][16][68];
    const int bm = blockIdx.x << 7;
    const int t  = threadIdx.x;
    const int ty = t >> 4, tx = t & 15;   // ty: 8-row group, tx: 4-col group
    const int am  = t >> 2;               // 0..63 (A load row within half)
    const int akq = (t & 3) << 2;         // 0,4,8,12
    const int bkk = t >> 4;               // 0..15
    const int bnq = (t & 15) << 2;

    ull acc[4][4];                        // [m-pair][n]
    #pragma unroll
    for (int p = 0; p < 4; p++)
        #pragma unroll
        for (int n = 0; n < 4; n++) acc[p][n] = 0ull;

    float4 sA0, sA1, sB;
    // prologue: load tile 0
    sA0 = *(const float4*)(A + (size_t)(bm + am)      * 512 + akq);
    sA1 = *(const float4*)(A + (size_t)(bm + 64 + am) * 512 + akq);
    sB  = *(const float4*)(Bw + (size_t)bkk * 64 + bnq);
    {
        As[0][akq + 0][am] = sA0.x; As[0][akq + 1][am] = sA0.y;
        As[0][akq + 2][am] = sA0.z; As[0][akq + 3][am] = sA0.w;
        As[0][akq + 0][64 + am] = sA1.x; As[0][akq + 1][64 + am] = sA1.y;
        As[0][akq + 2][64 + am] = sA1.z; As[0][akq + 3][64 + am] = sA1.w;
        *(float4*)&Bs[0][bkk][bnq] = sB;
    }
    __syncthreads();

    for (int tt = 0; tt < 32; tt++) {
        const int buf = tt & 1;
        if (tt + 1 < 32) {   // prefetch next tile into registers
            const int k0 = (tt + 1) << 4;
            sA0 = *(const float4*)(A + (size_t)(bm + am)      * 512 + k0 + akq);
            sA1 = *(const float4*)(A + (size_t)(bm + 64 + am) * 512 + k0 + akq);
            sB  = *(const float4*)(Bw + (size_t)(k0 + bkk) * 64 + bnq);
        }
        #pragma unroll
        for (int kk = 0; kk < 16; kk++) {
            const longlong2 ap0 = *(const longlong2*)&As[buf][kk][ty << 3];
            const longlong2 ap1 = *(const longlong2*)&As[buf][kk][(ty << 3) + 4];
            const float4 bv = *(const float4*)&Bs[buf][kk][tx << 2];
            const ull b0 = pk2(bv.x, bv.x), b1 = pk2(bv.y, bv.y);
            const ull b2 = pk2(bv.z, bv.z), b3 = pk2(bv.w, bv.w);
            const ull a0 = (ull)ap0.x, a1 = (ull)ap0.y;
            const ull a2 = (ull)ap1.x, a3 = (ull)ap1.y;
            acc[0][0] = fma2(a0, b0, acc[0][0]); acc[0][1] = fma2(a0, b1, acc[0][1]);
            acc[0][2] = fma2(a0, b2, acc[0][2]); acc[0][3] = fma2(a0, b3, acc[0][3]);
            acc[1][0] = fma2(a1, b0, acc[1][0]); acc[1][1] = fma2(a1, b1, acc[1][1]);
            acc[1][2] = fma2(a1, b2, acc[1][2]); acc[1][3] = fma2(a1, b3, acc[1][3]);
            acc[2][0] = fma2(a2, b0, acc[2][0]); acc[2][1] = fma2(a2, b1, acc[2][1]);
            acc[2][2] = fma2(a2, b2, acc[2][2]); acc[2][3] = fma2(a2, b3, acc[2][3]);
            acc[3][0] = fma2(a3, b0, acc[3][0]); acc[3][1] = fma2(a3, b1, acc[3][1]);
            acc[3][2] = fma2(a3, b2, acc[3][2]); acc[3][3] = fma2(a3, b3, acc[3][3]);
        }
        if (tt + 1 < 32) {   // store prefetched tile into the other buffer
            const int nb = buf ^ 1;
            As[nb][akq + 0][am] = sA0.x; As[nb][akq + 1][am] = sA0.y;
            As[nb][akq + 2][am] = sA0.z; As[nb][akq + 3][am] = sA0.w;
            As[nb][akq + 0][64 + am] = sA1.x; As[nb][akq + 1][64 + am] = sA1.y;
            As[nb][akq + 2][64 + am] = sA1.z; As[nb][akq + 3][64 + am] = sA1.w;
            *(float4*)&Bs[nb][bkk][bnq] = sB;
        }
        __syncthreads();
    }
    // epilogue: each m-pair p -> rows bm + ty*8 + 2p (+1)
    #pragma unroll
    for (int p = 0; p < 4; p++) {
        float l0, h0, l1, h1, l2, h2, l3, h3;
        upk2(acc[p][0], l0, h0); upk2(acc[p][1], l1, h1);
        upk2(acc[p][2], l2, h2); upk2(acc[p][3], l3, h3);
        const int m0 = bm + (ty << 3) + (p << 1);
        *(float4*)(C + (size_t)m0 * 64 + (tx << 2))       = make_float4(l0, l1, l2, l3);
        *(float4*)(C + (size_t)(m0 + 1) * 64 + (tx << 2)) = make_float4(h0, h1, h2, h3);
    }
}

// ---------------- kernel 3: s/d projections, stored NODE-MAJOR [row][h] ---------
template<int LAYER>
__global__ void __launch_bounds__(256) k_sd(const float* __restrict__ asrc,
                                            const float* __restrict__ adst) {
    const float* __restrict__ hp = (LAYER == 0) ? g_hp0 : g_hp1;
    float* __restrict__ s = (LAYER == 0) ? g_s0t : g_s1t;
    float* __restrict__ d = (LAYER == 0) ? g_d0t : g_d1t;
    const int row  = (blockIdx.x << 3) + (threadIdx.x >> 5);
    const int lane = threadIdx.x & 31;
    const float h0 = hp[(size_t)row * 64 + lane];
    const float h1 = hp[(size_t)row * 64 + 32 + lane];
    float ps[8], pd[8];
    #pragma unroll
    for (int h = 0; h < 8; h++) {
        ps[h] = h0 * asrc[(lane << 3) + h] + h1 * asrc[((lane + 32) << 3) + h];
        pd[h] = h0 * adst[(lane << 3) + h] + h1 * adst[((lane + 32) << 3) + h];
    }
    #pragma unroll
    for (int h = 0; h < 8; h++) {
        #pragma unroll
        for (int o = 16; o; o >>= 1) {
            ps[h] += __shfl_xor_sync(0xffffffffu, ps[h], o);
            pd[h] += __shfl_xor_sync(0xffffffffu, pd[h], o);
        }
    }
    if (lane == 0) {
        *(float4*)(s + (row << 3))     = make_float4(ps[0], ps[1], ps[2], ps[3]);
        *(float4*)(s + (row << 3) + 4) = make_float4(ps[4], ps[5], ps[6], ps[7]);
        *(float4*)(d + (row << 3))     = make_float4(pd[0], pd[1], pd[2], pd[3]);
        *(float4*)(d + (row << 3) + 4) = make_float4(pd[4], pd[5], pd[6], pd[7]);
    }
}

// ---------------- kernel 4: layer-1 one-pass aggregate --------------------------
__global__ void __launch_bounds__(128, 8) k_agg1() {
    __shared__ __align__(16) float4 s_dA[NN], s_dB[NN];  // d[b][j][0:4], [4:8]
    __shared__ __align__(16) float  s_w[4][32][8];       // weights, un-duplicated
    __shared__ __align__(16) int    s_off[4][32];        // hp byte offsets (j<<8)
    const int w = threadIdx.x >> 5, lane = threadIdx.x & 31;
    const int row = (blockIdx.x << 2) + w;
    const int b = row >> 9, i = row & (NN - 1);
    const int cnt = g_cnt[row];
    const int16_t* __restrict__ nbrrow = g_nbr + ((size_t)row << 9);
    const char*  __restrict__ hpl =
        (const char*)(g_hp0 + ((size_t)b << 15)) + (lane << 3);  // lane's 8B in row

    {
        const float4* src = (const float4*)(g_d0t + ((size_t)b << 12));
        #pragma unroll
        for (int t = 0; t < 8; t++) {
            const int e = threadIdx.x + (t << 7);   // 0..1023
            const float4 v = src[e];
            if (e & 1) s_dB[e >> 1] = v; else s_dA[e >> 1] = v;
        }
    }
    __syncthreads();

    float sh[8], Zl[8];
    {
        const float4 s0 = *(const float4*)(g_s0t + (row << 3));
        const float4 s1 = *(const float4*)(g_s0t + (row << 3) + 4);
        sh[0] = s0.x; sh[1] = s0.y; sh[2] = s0.z; sh[3] = s0.w;
        sh[4] = s1.x; sh[5] = s1.y; sh[6] = s1.z; sh[7] = s1.w;
    }
    ull acc[8];
    #pragma unroll
    for (int h = 0; h < 8; h++) { Zl[h] = 0.f; acc[h] = 0ull; }

    for (int base = 0; base < cnt; base += 32) {
        const int nc = min(32, cnt - base);
        float wt[8];
        #pragma unroll
        for (int h = 0; h < 8; h++) wt[h] = 0.f;
        int off = i << 8;
        if (lane < nc) {
            const int j = (int)nbrrow[base + lane];
            off = j << 8;
            const float4 da = s_dA[j];
            const float4 db = s_dB[j];
            float dv[8] = {da.x, da.y, da.z, da.w, db.x, db.y, db.z, db.w};
            #pragma unroll
            for (int h = 0; h < 8; h++) {
                const float ev = sh[h] + dv[h];
                const float lv = fmaxf(ev, 0.2f * ev);
                const float e  = (lv != 0.f) ? __expf(lv) : 0.f;
                wt[h] = e;
                Zl[h] += e;
            }
        }
        s_off[w][lane] = off;
        {
            float4* wp = (float4*)&s_w[w][lane][0];
            wp[0] = make_float4(wt[0], wt[1], wt[2], wt[3]);
            wp[1] = make_float4(wt[4], wt[5], wt[6], wt[7]);
        }
        __syncwarp();
        for (int g = 0; g < nc; g += 8) {
            const int4 of0 = *(const int4*)&s_off[w][g];
            const int4 of1 = *(const int4*)&s_off[w][g + 4];
            ull hpv[8];
            hpv[0] = *(const ull*)(hpl + of0.x);
            hpv[1] = *(const ull*)(hpl + of0.y);
            hpv[2] = *(const ull*)(hpl + of0.z);
            hpv[3] = *(const ull*)(hpl + of0.w);
            hpv[4] = *(const ull*)(hpl + of1.x);
            hpv[5] = *(const ull*)(hpl + of1.y);
            hpv[6] = *(const ull*)(hpl + of1.z);
            hpv[7] = *(const ull*)(hpl + of1.w);
            #pragma unroll
            for (int q = 0; q < 8; q++) {
                const float4 wa = *(const float4*)&s_w[w][g + q][0];
                const float4 wb = *(const float4*)&s_w[w][g + q][4];
                acc[0] = fma2(pk2(wa.x, wa.x), hpv[q], acc[0]);
                acc[1] = fma2(pk2(wa.y, wa.y), hpv[q], acc[1]);
                acc[2] = fma2(pk2(wa.z, wa.z), hpv[q], acc[2]);
                acc[3] = fma2(pk2(wa.w, wa.w), hpv[q], acc[3]);
                acc[4] = fma2(pk2(wb.x, wb.x), hpv[q], acc[4]);
                acc[5] = fma2(pk2(wb.y, wb.y), hpv[q], acc[5]);
                acc[6] = fma2(pk2(wb.z, wb.z), hpv[q], acc[6]);
                acc[7] = fma2(pk2(wb.w, wb.w), hpv[q], acc[7]);
            }
        }
        __syncwarp();
    }
    #pragma unroll
    for (int h = 0; h < 8; h++)
        #pragma unroll
        for (int o = 16; o; o >>= 1)
            Zl[h] += __shfl_xor_sync(0xffffffffu, Zl[h], o);
    float* xout = g_x1 + ((size_t)row << 9);
    #pragma unroll
    for (int h = 0; h < 8; h++) {
        const float rz = __fdividef(1.f, Zl[h]);
        float xf, yf; upk2(mul2(acc[h], pk2(rz, rz)), xf, yf);
        xf = xf > 0.f ? xf : (__expf(xf) - 1.f);
        yf = yf > 0.f ? yf : (__expf(yf) - 1.f);
        ((float2*)(xout + (h << 6)))[lane] = make_float2(xf, yf);
    }
}

// ---------------- kernel 5: layer-2 two-pass, d[b] staged (split) in SMEM -------
__global__ void __launch_bounds__(128, 8) k_agg2(float* __restrict__ out) {
    __shared__ __align__(16) float4 s_dA[NN], s_dB[NN];
    __shared__ __align__(16) float  s_wb[4][32];
    __shared__ __align__(16) int    s_off[4][32];
    const int w = threadIdx.x >> 5, lane = threadIdx.x & 31;
    const int row = (blockIdx.x << 2) + w;
    const int b = row >> 9, i = row & (NN - 1);
    const int cnt = g_cnt[row];
    const int16_t* __restrict__ nbrrow = g_nbr + ((size_t)row << 9);
    const char*  __restrict__ hpl =
        (const char*)(g_hp1 + ((size_t)b << 15)) + (lane << 3);

    {
        const float4* src = (const float4*)(g_d1t + ((size_t)b << 12));
        #pragma unroll
        for (int t = 0; t < 8; t++) {
            const int e = threadIdx.x + (t << 7);
            const float4 v = src[e];
            if (e & 1) s_dB[e >> 1] = v; else s_dA[e >> 1] = v;
        }
    }
    __syncthreads();

    float sh[8], Zl[8];
    {
        const float4 s0 = *(const float4*)(g_s1t + (row << 3));
        const float4 s1 = *(const float4*)(g_s1t + (row << 3) + 4);
        sh[0] = s0.x; sh[1] = s0.y; sh[2] = s0.z; sh[3] = s0.w;
        sh[4] = s1.x; sh[5] = s1.y; sh[6] = s1.z; sh[7] = s1.w;
    }
    #pragma unroll
    for (int h = 0; h < 8; h++) Zl[h] = 0.f;

    #pragma unroll 2
    for (int p = lane; p < cnt; p += 32) {
        const int j = (int)nbrrow[p];
        const float4 da = s_dA[j];
        const float4 db = s_dB[j];
        float dv[8] = {da.x, da.y, da.z, da.w, db.x, db.y, db.z, db.w};
        #pragma unroll
        for (int h = 0; h < 8; h++) {
            const float ev = sh[h] + dv[h];
            const float lv = fmaxf(ev, 0.2f * ev);
            if (lv != 0.f) Zl[h] += __expf(lv);
        }
    }
    #pragma unroll
    for (int h = 0; h < 8; h++)
        #pragma unroll
        for (int o = 16; o; o >>= 1)
            Zl[h] += __shfl_xor_sync(0xffffffffu, Zl[h], o);
    float rz8[8];
    #pragma unroll
    for (int h = 0; h < 8; h++) rz8[h] = __fdividef(0.125f, Zl[h]);

    ull acc = 0ull;
    for (int base = 0; base < cnt; base += 32) {
        const int nc = min(32, cnt - base);
        float ws = 0.f;
        int off = i << 8;
        if (lane < nc) {
            const int j = (int)nbrrow[base + lane];
            off = j << 8;
            const float4 da = s_dA[j];
            const float4 db = s_dB[j];
            float dv[8] = {da.x, da.y, da.z, da.w, db.x, db.y, db.z, db.w};
            #pragma unroll
            for (int h = 0; h < 8; h++) {
                const float ev = sh[h] + dv[h];
                const float lv = fmaxf(ev, 0.2f * ev);
                if (lv != 0.f) ws += __expf(lv) * rz8[h];
            }
        }
        s_off[w][lane] = off;
        s_wb[w][lane] = ws;
        __syncwarp();
        for (int g = 0; g < nc; g += 8) {
            const int4 of0 = *(const int4*)&s_off[w][g];
            const int4 of1 = *(const int4*)&s_off[w][g + 4];
            const float4 wv0 = *(const float4*)&s_wb[w][g];
            const float4 wv1 = *(const float4*)&s_wb[w][g + 4];
            ull hpv[8];
            hpv[0] = *(const ull*)(hpl + of0.x);
            hpv[1] = *(const ull*)(hpl + of0.y);
            hpv[2] = *(const ull*)(hpl + of0.z);
            hpv[3] = *(const ull*)(hpl + of0.w);
            hpv[4] = *(const ull*)(hpl + of1.x);
            hpv[5] = *(const ull*)(hpl + of1.y);
            hpv[6] = *(const ull*)(hpl + of1.z);
            hpv[7] = *(const ull*)(hpl + of1.w);
            acc = fma2(pk2(wv0.x, wv0.x), hpv[0], acc);
            acc = fma2(pk2(wv0.y, wv0.y), hpv[1], acc);
            acc = fma2(pk2(wv0.z, wv0.z), hpv[2], acc);
            acc = fma2(pk2(wv0.w, wv0.w), hpv[3], acc);
            acc = fma2(pk2(wv1.x, wv1.x), hpv[4], acc);
            acc = fma2(pk2(wv1.y, wv1.y), hpv[5], acc);
            acc = fma2(pk2(wv1.z, wv1.z), hpv[6], acc);
            acc = fma2(pk2(wv1.w, wv1.w), hpv[7], acc);
        }
        __syncwarp();
    }
    float xf, yf; upk2(acc, xf, yf);
    ((float2*)(out + ((size_t)row << 6)))[lane] = make_float2(xf, yf);
}

// ---------------- launch --------------------------------------------------------
extern "C" void kernel_launch(void* const* d_in, const int* in_sizes, int n_in,
                              void* d_out, int out_size) {
    const float* x     = (const float*)d_in[0];
    const float* adj   = (const float*)d_in[1];
    const float* W0    = (const float*)d_in[4];
    const float* asrc0 = (const float*)d_in[5];
    const float* adst0 = (const float*)d_in[6];
    const float* W1    = (const float*)d_in[7];
    const float* asrc1 = (const float*)d_in[8];
    const float* adst1 = (const float*)d_in[9];
    float* out = (float*)d_out;

    k_build_nbr<<<ROWS / 8, 256>>>(adj);
    k_gemm0<<<ROWS / 64, 256>>>(x, W0);
    k_sd<0><<<ROWS / 8, 256>>>(asrc0, adst0);
    k_agg1<<<ROWS / 4, 128>>>();
    k_gemm1<<<ROWS / 128, 256>>>(W1);
    k_sd<1><<<ROWS / 8, 256>>>(asrc1, adst1);
    k_agg2<<<ROWS / 4, 128>>>(out);
}